// round 5
// baseline (speedup 1.0000x reference)
#include <cuda_runtime.h>
#include <math.h>

#define BB 4
#define NN 16384
#define DIMM 256
#define HH 8
#define DD 64
#define SS 64
#define INNERR 512

// ---------------- device scratch (static allocation is allowed) ----------------
__device__ float g_CWT[HH * DIMM * 128];               // combined weight, [h][k][col] (col<64: Wfx_h, col>=64: P_h/temp)
__device__ float g_Cb[HH * 128];                       // combined bias
__device__ float g_w[(size_t)BB * NN * HH * SS];       // softmax slice weights [b][n][h][s]  (= [b][n][j])
__device__ float g_tok[BB * HH * SS * DD];             // accumulated tok (atomics)
__device__ float g_norm[BB * HH * SS];                 // slice_norm (atomics)
__device__ float g_ot[BB * HH * SS * DD];              // out_tok
__device__ float g_MT[BB * INNERR * DIMM];             // M^T: [b][j=h*64+s][o]

// ---------------- zero accumulators ----------------
__global__ void kz() {
    int i = blockIdx.x * blockDim.x + threadIdx.x;
    if (i < BB * HH * SS * DD) g_tok[i] = 0.f;
    if (i < BB * HH * SS) g_norm[i] = 0.f;
}

// ---------------- prep: build combined (pre-transposed) weights ----------------
// grid (H, DIM), block 128 (one thread per output col)
__global__ void k_prep(const float* __restrict__ Wx, const float* __restrict__ bx,
                       const float* __restrict__ Wfx, const float* __restrict__ bfx,
                       const float* __restrict__ Wslice, const float* __restrict__ bslice,
                       const float* __restrict__ temperature) {
    int h = blockIdx.x;
    int k = blockIdx.y;       // 0..255
    int col = threadIdx.x;    // 0..127
    float invt = 1.f / fmaxf(temperature[h], 1e-4f);
    float v;
    if (col < 64) {
        v = Wfx[(h * 64 + col) * DIMM + k];
    } else {
        int s = col - 64;
        float acc = 0.f;
        #pragma unroll 8
        for (int d = 0; d < 64; d++)
            acc += Wslice[s * 64 + d] * Wx[(h * 64 + d) * DIMM + k];
        v = acc * invt;
    }
    g_CWT[(h * DIMM + k) * 128 + col] = v;
    if (k == 0) {
        float bv;
        if (col < 64) {
            bv = bfx[h * 64 + col];
        } else {
            int s = col - 64;
            float acc = bslice[s];
            #pragma unroll 8
            for (int d = 0; d < 64; d++) acc += Wslice[s * 64 + d] * bx[h * 64 + d];
            bv = acc * invt;
        }
        g_Cb[h * 128 + col] = bv;
    }
}

// ---------------- pass 1: fused fx/logit GEMM + softmax + tok accumulation ----------------
// grid (H, N/64, B), block 256, dynamic smem = (64*260 + 64*132)*4 = 100352 B
__global__ __launch_bounds__(256, 2) void k1(const float* __restrict__ x) {
    extern __shared__ float sm[];
    float* xs = sm;                 // [64][260] x tile
    float* ws = sm + 64 * 260;      // [64][132] weight chunk, [kk][col]
    const int h = blockIdx.x, nt = blockIdx.y, b = blockIdx.z;
    const int tid = threadIdx.x;
    const int tx = tid & 15, ty = tid >> 4;
    const int n0 = nt * 64;

    const float* xp = x + (size_t)(b * NN + n0) * DIMM;
    for (int i = tid; i < 64 * 64; i += 256) {
        int t = i >> 6, c4 = i & 63;
        float4 v = ((const float4*)xp)[t * 64 + c4];
        *(float4*)(xs + t * 260 + c4 * 4) = v;
    }

    float acc[32];
    #pragma unroll
    for (int i = 0; i < 32; i++) acc[i] = 0.f;

    const float* cwt = g_CWT + h * DIMM * 128;
    for (int kc = 0; kc < DIMM; kc += 64) {
        __syncthreads();
        for (int i = tid; i < 64 * 32; i += 256) {
            int kk = i >> 5, c4 = i & 31;
            *(float4*)(ws + kk * 132 + c4 * 4) = ((const float4*)(cwt + (kc + kk) * 128))[c4];
        }
        __syncthreads();
        #pragma unroll 8
        for (int kk = 0; kk < 64; kk++) {
            float a[4];
            #pragma unroll
            for (int i = 0; i < 4; i++) a[i] = xs[(ty * 4 + i) * 260 + kc + kk];
            float4 b0 = *(const float4*)(ws + kk * 132 + tx * 4);
            float4 b1 = *(const float4*)(ws + kk * 132 + 64 + tx * 4);
            #pragma unroll
            for (int i = 0; i < 4; i++) {
                acc[i * 8 + 0] += a[i] * b0.x;
                acc[i * 8 + 1] += a[i] * b0.y;
                acc[i * 8 + 2] += a[i] * b0.z;
                acc[i * 8 + 3] += a[i] * b0.w;
                acc[i * 8 + 4] += a[i] * b1.x;
                acc[i * 8 + 5] += a[i] * b1.y;
                acc[i * 8 + 6] += a[i] * b1.z;
                acc[i * 8 + 7] += a[i] * b1.w;
            }
        }
    }
    __syncthreads();

    // epilogue: bias + stage fx and logits (reuse xs region)
    float* fxs = sm;             // [64][68]
    float* lgs = sm + 64 * 68;   // [64][68]
    {
        const float* cb = g_Cb + h * 128;
        float bf[4], bl[4];
        #pragma unroll
        for (int j = 0; j < 4; j++) { bf[j] = cb[tx * 4 + j]; bl[j] = cb[64 + tx * 4 + j]; }
        #pragma unroll
        for (int i = 0; i < 4; i++) {
            int t = ty * 4 + i;
            #pragma unroll
            for (int j = 0; j < 4; j++) {
                fxs[t * 68 + tx * 4 + j] = acc[i * 8 + j] + bf[j];
                lgs[t * 68 + tx * 4 + j] = acc[i * 8 + 4 + j] + bl[j];
            }
        }
    }
    __syncthreads();

    // softmax over S=64 per token; 4 threads per token
    {
        int tok = tid >> 2, q4 = tid & 3;
        float* row = lgs + tok * 68;
        float m = -1e30f;
        #pragma unroll
        for (int s = 0; s < 16; s++) m = fmaxf(m, row[q4 * 16 + s]);
        m = fmaxf(m, __shfl_xor_sync(0xffffffffu, m, 1));
        m = fmaxf(m, __shfl_xor_sync(0xffffffffu, m, 2));
        float e[16];
        float sum = 0.f;
        #pragma unroll
        for (int s = 0; s < 16; s++) { e[s] = __expf(row[q4 * 16 + s] - m); sum += e[s]; }
        sum += __shfl_xor_sync(0xffffffffu, sum, 1);
        sum += __shfl_xor_sync(0xffffffffu, sum, 2);
        float inv = 1.f / sum;
        #pragma unroll
        for (int s = 0; s < 16; s++) row[q4 * 16 + s] = e[s] * inv;
        // write w: [b][n][h][s] = [b][n][j] layout for pass-2 GEMM
        float* gw = g_w + (((size_t)b * NN + n0 + tok) * HH + h) * SS + q4 * 16;
        #pragma unroll
        for (int s4 = 0; s4 < 4; s4++)
            ((float4*)gw)[s4] = *(float4*)(row + q4 * 16 + s4 * 4);
    }
    __syncthreads();

    // slice_norm accumulation
    if (tid < 64) {
        float ns = 0.f;
        for (int t = 0; t < 64; t++) ns += lgs[t * 68 + tid];
        atomicAdd(&g_norm[((size_t)b * HH + h) * 64 + tid], ns);
    }

    // tok[s][d] += sum_t w[t][s] * fx[t][d]
    float tacc[16];
    #pragma unroll
    for (int i = 0; i < 16; i++) tacc[i] = 0.f;
    for (int t = 0; t < 64; t++) {
        float4 bb = *(const float4*)(fxs + t * 68 + tx * 4);
        #pragma unroll
        for (int i = 0; i < 4; i++) {
            float a = lgs[t * 68 + ty * 4 + i];
            tacc[i * 4 + 0] += a * bb.x;
            tacc[i * 4 + 1] += a * bb.y;
            tacc[i * 4 + 2] += a * bb.z;
            tacc[i * 4 + 3] += a * bb.w;
        }
    }
    float* gt = g_tok + (size_t)((b * HH + h) * 64) * 64;
    #pragma unroll
    for (int i = 0; i < 4; i++)
        #pragma unroll
        for (int j = 0; j < 4; j++)
            atomicAdd(gt + (ty * 4 + i) * 64 + tx * 4 + j, tacc[i * 4 + j]);
}

// ---------------- tiny cross-slice attention ----------------
// grid (H, B), block 256, dynamic smem = (7*4160 + 128)*4 = 116992 B
__global__ void k2(const float* __restrict__ Wq, const float* __restrict__ Wk,
                   const float* __restrict__ Wv, const float* __restrict__ ascale_p,
                   const float* __restrict__ srs_p) {
    extern __shared__ float sm[];
    float* tokn = sm;
    float* kv   = sm + 4160;
    float* qq   = sm + 2 * 4160;
    float* kk_  = sm + 3 * 4160;
    float* vv   = sm + 4 * 4160;
    float* att  = sm + 5 * 4160;
    float* wsm  = sm + 6 * 4160;
    float* nq   = sm + 7 * 4160;
    float* nk   = nq + 64;
    const int h = blockIdx.x, b = blockIdx.y;
    const int tid = threadIdx.x;

    // normalized tok for this head + kv = mean over heads of normalized tok
    for (int i = tid; i < 4096; i += 256) {
        int s = i >> 6, d = i & 63;
        float accv = 0.f;
        #pragma unroll
        for (int hh = 0; hh < 8; hh++) {
            float nv = g_norm[(b * 8 + hh) * 64 + s] + 1e-5f;
            accv += g_tok[((b * 8 + hh) * 64 + s) * 64 + d] / nv;
        }
        kv[s * 65 + d] = accv * 0.125f;
        float nv = g_norm[(b * 8 + h) * 64 + s] + 1e-5f;
        tokn[s * 65 + d] = g_tok[((b * 8 + h) * 64 + s) * 64 + d] / nv;
    }
    __syncthreads();

    // q = tokn @ Wq^T
    for (int i = tid; i < 4096; i += 256) wsm[(i >> 6) * 65 + (i & 63)] = Wq[i];
    __syncthreads();
    for (int i = tid; i < 4096; i += 256) {
        int g = i >> 6, d = i & 63;
        float a = 0.f;
        #pragma unroll 8
        for (int e = 0; e < 64; e++) a += tokn[g * 65 + e] * wsm[d * 65 + e];
        qq[g * 65 + d] = a;
    }
    __syncthreads();
    // k = kv @ Wk^T
    for (int i = tid; i < 4096; i += 256) wsm[(i >> 6) * 65 + (i & 63)] = Wk[i];
    __syncthreads();
    for (int i = tid; i < 4096; i += 256) {
        int s = i >> 6, d = i & 63;
        float a = 0.f;
        #pragma unroll 8
        for (int e = 0; e < 64; e++) a += kv[s * 65 + e] * wsm[d * 65 + e];
        kk_[s * 65 + d] = a;
    }
    __syncthreads();
    // v = kv @ Wv^T
    for (int i = tid; i < 4096; i += 256) wsm[(i >> 6) * 65 + (i & 63)] = Wv[i];
    __syncthreads();
    for (int i = tid; i < 4096; i += 256) {
        int s = i >> 6, d = i & 63;
        float a = 0.f;
        #pragma unroll 8
        for (int e = 0; e < 64; e++) a += kv[s * 65 + e] * wsm[d * 65 + e];
        vv[s * 65 + d] = a;
    }
    __syncthreads();

    // row norms for cosine attention
    if (tid < 64) {
        float s2 = 0.f;
        #pragma unroll 8
        for (int d = 0; d < 64; d++) { float v = qq[tid * 65 + d]; s2 += v * v; }
        nq[tid] = fmaxf(sqrtf(s2), 1e-12f);
    } else if (tid < 128) {
        int t2 = tid - 64;
        float s2 = 0.f;
        #pragma unroll 8
        for (int d = 0; d < 64; d++) { float v = kk_[t2 * 65 + d]; s2 += v * v; }
        nk[t2] = fmaxf(sqrtf(s2), 1e-12f);
    }
    __syncthreads();

    float asc = ascale_p[h];
    for (int i = tid; i < 4096; i += 256) {
        int g = i >> 6, s = i & 63;
        float a = 0.f;
        #pragma unroll 8
        for (int e = 0; e < 64; e++) a += qq[g * 65 + e] * kk_[s * 65 + e];
        att[g * 65 + s] = a * asc / (nq[g] * nk[s]);
    }
    __syncthreads();

    // softmax rows of att
    {
        int g = tid >> 2, q4 = tid & 3;
        float* row = att + g * 65;
        float m = -1e30f;
        #pragma unroll
        for (int s = 0; s < 16; s++) m = fmaxf(m, row[q4 * 16 + s]);
        m = fmaxf(m, __shfl_xor_sync(0xffffffffu, m, 1));
        m = fmaxf(m, __shfl_xor_sync(0xffffffffu, m, 2));
        float e[16];
        float sum = 0.f;
        #pragma unroll
        for (int s = 0; s < 16; s++) { e[s] = __expf(row[q4 * 16 + s] - m); sum += e[s]; }
        sum += __shfl_xor_sync(0xffffffffu, sum, 1);
        sum += __shfl_xor_sync(0xffffffffu, sum, 2);
        float inv = 1.f / sum;
        #pragma unroll
        for (int s = 0; s < 16; s++) row[q4 * 16 + s] = e[s] * inv;
    }
    __syncthreads();

    float sr = srs_p[0];
    for (int i = tid; i < 4096; i += 256) {
        int g = i >> 6, d = i & 63;
        float a = 0.f;
        #pragma unroll 8
        for (int s2 = 0; s2 < 64; s2++) a += att[g * 65 + s2] * vv[s2 * 65 + d];
        g_ot[((b * 8 + h) * 64 + g) * 64 + d] = a + sr * tokn[g * 65 + d];
    }
}

// ---------------- M^T precompute: MT[b][j=h*64+s][o] = sum_d Wout[o][h*64+d] * ot[b][h][s][d] ----------------
// grid (32, B), block 256
__global__ void k2b(const float* __restrict__ Wout) {
    __shared__ float ots[16 * 64];
    const int b = blockIdx.y;
    const int j0 = blockIdx.x * 16;
    const int tid = threadIdx.x;
    for (int i = tid; i < 16 * 64; i += 256) {
        int jj = i >> 6, d = i & 63;
        int j = j0 + jj, h = j >> 6, s = j & 63;
        ots[jj * 64 + d] = g_ot[((b * 8 + h) * 64 + s) * 64 + d];
    }
    __syncthreads();
    int o = tid;  // 0..255
    int h = j0 >> 6;
    #pragma unroll 4
    for (int jj = 0; jj < 16; jj++) {
        float acc = 0.f;
        #pragma unroll 8
        for (int d = 0; d < 64; d++)
            acc += Wout[(size_t)o * INNERR + h * 64 + d] * ots[jj * 64 + d];
        g_MT[((size_t)b * INNERR + j0 + jj) * DIMM + o] = acc;
    }
}

// ---------------- pass 2: y = w @ M^T + bout   ([N,512] x [512,256] per batch) ----------------
// grid (2, N/64, B), block 256, dynamic smem = (64*68 + 64*132)*4 = 51200 B
__global__ __launch_bounds__(256, 2) void k3(const float* __restrict__ bout, float* __restrict__ out) {
    extern __shared__ float sm[];
    float* wt = sm;             // [64][68]
    float* ms = sm + 64 * 68;   // [64][132]
    const int cb = blockIdx.x, nt = blockIdx.y, b = blockIdx.z;
    const int tid = threadIdx.x, tx = tid & 15, ty = tid >> 4;
    const int n0 = nt * 64, col0 = cb * 128;
    const float* wp = g_w + (size_t)(b * NN + n0) * INNERR;
    const float* mp = g_MT + (size_t)b * INNERR * DIMM;

    float acc[32];
    #pragma unroll
    for (int i = 0; i < 32; i++) acc[i] = 0.f;

    for (int kc = 0; kc < INNERR; kc += 64) {
        __syncthreads();
        for (int i = tid; i < 1024; i += 256) {
            int t = i >> 4, k4 = i & 15;
            *(float4*)(wt + t * 68 + k4 * 4) = *(const float4*)(wp + (size_t)t * INNERR + kc + k4 * 4);
        }
        for (int i = tid; i < 2048; i += 256) {
            int kk = i >> 5, c4 = i & 31;
            *(float4*)(ms + kk * 132 + c4 * 4) = *(const float4*)(mp + (size_t)(kc + kk) * DIMM + col0 + c4 * 4);
        }
        __syncthreads();
        #pragma unroll 8
        for (int kk = 0; kk < 64; kk++) {
            float a[4];
            #pragma unroll
            for (int i = 0; i < 4; i++) a[i] = wt[(ty * 4 + i) * 68 + kk];
            float4 b0 = *(const float4*)(ms + kk * 132 + tx * 4);
            float4 b1 = *(const float4*)(ms + kk * 132 + 64 + tx * 4);
            #pragma unroll
            for (int i = 0; i < 4; i++) {
                acc[i * 8 + 0] += a[i] * b0.x;
                acc[i * 8 + 1] += a[i] * b0.y;
                acc[i * 8 + 2] += a[i] * b0.z;
                acc[i * 8 + 3] += a[i] * b0.w;
                acc[i * 8 + 4] += a[i] * b1.x;
                acc[i * 8 + 5] += a[i] * b1.y;
                acc[i * 8 + 6] += a[i] * b1.z;
                acc[i * 8 + 7] += a[i] * b1.w;
            }
        }
    }

    float4 ba0 = *(const float4*)(bout + col0 + tx * 4);
    float4 ba1 = *(const float4*)(bout + col0 + 64 + tx * 4);
    #pragma unroll
    for (int i = 0; i < 4; i++) {
        float* orow = out + (size_t)(b * NN + n0 + ty * 4 + i) * DIMM + col0;
        float4 v0 = make_float4(acc[i * 8 + 0] + ba0.x, acc[i * 8 + 1] + ba0.y,
                                acc[i * 8 + 2] + ba0.z, acc[i * 8 + 3] + ba0.w);
        float4 v1 = make_float4(acc[i * 8 + 4] + ba1.x, acc[i * 8 + 5] + ba1.y,
                                acc[i * 8 + 6] + ba1.z, acc[i * 8 + 7] + ba1.w);
        *(float4*)(orow + tx * 4) = v0;
        *(float4*)(orow + 64 + tx * 4) = v1;
    }
}

// ---------------- launch ----------------
extern "C" void kernel_launch(void* const* d_in, const int* in_sizes, int n_in,
                              void* d_out, int out_size) {
    const float* x           = (const float*)d_in[0];
    const float* Wx          = (const float*)d_in[1];
    const float* bx          = (const float*)d_in[2];
    const float* Wfx         = (const float*)d_in[3];
    const float* bfx         = (const float*)d_in[4];
    const float* Wslice      = (const float*)d_in[5];
    const float* bslice      = (const float*)d_in[6];
    const float* temperature = (const float*)d_in[7];
    const float* Wq          = (const float*)d_in[8];
    const float* Wk          = (const float*)d_in[9];
    const float* Wv          = (const float*)d_in[10];
    const float* attn_scale  = (const float*)d_in[11];
    const float* srs         = (const float*)d_in[12];
    const float* Wout        = (const float*)d_in[13];
    const float* bout        = (const float*)d_in[14];
    float* out = (float*)d_out;

    const int K1S = (64 * 260 + 64 * 132) * (int)sizeof(float);   // 100352
    const int K2S = (7 * 4160 + 128) * (int)sizeof(float);        // 116992
    const int K3S = (64 * 68 + 64 * 132) * (int)sizeof(float);    // 51200
    cudaFuncSetAttribute(k1, cudaFuncAttributeMaxDynamicSharedMemorySize, K1S);
    cudaFuncSetAttribute(k2, cudaFuncAttributeMaxDynamicSharedMemorySize, K2S);
    cudaFuncSetAttribute(k3, cudaFuncAttributeMaxDynamicSharedMemorySize, K3S);

    kz<<<512, 256>>>();
    k_prep<<<dim3(HH, DIMM), 128>>>(Wx, bx, Wfx, bfx, Wslice, bslice, temperature);
    k1<<<dim3(HH, NN / 64, BB), 256, K1S>>>(x);
    k2<<<dim3(HH, BB), 256, K2S>>>(Wq, Wk, Wv, attn_scale, srs);
    k2b<<<dim3(32, BB), 256>>>(Wout);
    k3<<<dim3(2, NN / 64, BB), 256, K3S>>>(bout, out);
}

// round 8
// speedup vs baseline: 2.3602x; 2.3602x over previous
#include <cuda_runtime.h>
#include <math.h>
#include <stdint.h>

#define BB 4
#define NN 16384
#define DIMM 256
#define HH 8
#define DD 64
#define SS 64
#define INNERR 512

// ---------------- device scratch ----------------
__device__ float g_CWT[HH * DIMM * 128];               // combined weight [h][k][col], tf32-rounded
__device__ float g_Cb[HH * 128];                       // combined bias (fp32)
__device__ float g_w[(size_t)BB * NN * HH * SS];       // softmax slice weights [b][n][h*64+s], tf32-rounded
__device__ float g_tok[BB * HH * SS * DD];             // accumulated tok (atomics)
__device__ float g_norm[BB * HH * SS];                 // slice_norm (atomics)
__device__ float g_ot[BB * HH * SS * DD];              // out_tok
__device__ float g_MT[BB * INNERR * DIMM];             // M^T [b][j][o], tf32-rounded

// ---------------- helpers ----------------
__device__ __forceinline__ float tf32r(float f) {
    uint32_t u;
    asm("cvt.rna.tf32.f32 %0, %1;" : "=r"(u) : "f"(f));
    return __uint_as_float(u);
}
__device__ __forceinline__ uint32_t FB(float f) { return __float_as_uint(f); }

__device__ __forceinline__ void mmat(float* d, uint32_t a0, uint32_t a1, uint32_t a2, uint32_t a3,
                                     uint32_t b0, uint32_t b1) {
    asm volatile(
        "mma.sync.aligned.m16n8k8.row.col.f32.tf32.tf32.f32 "
        "{%0,%1,%2,%3},{%4,%5,%6,%7},{%8,%9},{%0,%1,%2,%3};"
        : "+f"(d[0]), "+f"(d[1]), "+f"(d[2]), "+f"(d[3])
        : "r"(a0), "r"(a1), "r"(a2), "r"(a3), "r"(b0), "r"(b1));
}

// ---------------- zero accumulators ----------------
__global__ void kz() {
    int i = blockIdx.x * blockDim.x + threadIdx.x;
    if (i < BB * HH * SS * DD) g_tok[i] = 0.f;
    if (i < BB * HH * SS) g_norm[i] = 0.f;
}

// ---------------- prep: combined (pre-transposed, tf32-rounded) weights ----------------
__global__ void k_prep(const float* __restrict__ Wx, const float* __restrict__ bx,
                       const float* __restrict__ Wfx, const float* __restrict__ bfx,
                       const float* __restrict__ Wslice, const float* __restrict__ bslice,
                       const float* __restrict__ temperature) {
    int h = blockIdx.x;
    int k = blockIdx.y;
    int col = threadIdx.x;
    float invt = 1.f / fmaxf(temperature[h], 1e-4f);
    float v;
    if (col < 64) {
        v = Wfx[(h * 64 + col) * DIMM + k];
    } else {
        int s = col - 64;
        float acc = 0.f;
        #pragma unroll 8
        for (int d = 0; d < 64; d++)
            acc += Wslice[s * 64 + d] * Wx[(h * 64 + d) * DIMM + k];
        v = acc * invt;
    }
    g_CWT[(h * DIMM + k) * 128 + col] = tf32r(v);
    if (k == 0) {
        float bv;
        if (col < 64) {
            bv = bfx[h * 64 + col];
        } else {
            int s = col - 64;
            float acc = bslice[s];
            #pragma unroll 8
            for (int d = 0; d < 64; d++) acc += Wslice[s * 64 + d] * bx[h * 64 + d];
            bv = acc * invt;
        }
        g_Cb[h * 128 + col] = bv;
    }
}

// ---------------- pass 1: tf32 mma GEMM + softmax + tok (mma) ----------------
// grid (H, N/128, B), block 256, dyn smem = 2*128*72*4 = 73728 B
// GEMM phase smem: xs[128][68] + ws[64][136]; epilogue: fxs[128][72] + lgs[128][72]
__global__ __launch_bounds__(256, 2) void k1(const float* __restrict__ x) {
    extern __shared__ float sm[];
    float* xs = sm;                 // [128][68] tf32
    float* ws = sm + 128 * 68;      // [64][136] tf32
    const int h = blockIdx.x, nt = blockIdx.y, b = blockIdx.z;
    const int tid = threadIdx.x;
    const int lane = tid & 31, w = tid >> 5;
    const int wm = w & 3, wn = w >> 2;      // m group (32 tokens), col half (64 cols)
    const int g = lane >> 2, k4 = lane & 3;
    const int n0 = nt * 128;

    const float* xp = x + (size_t)(b * NN + n0) * DIMM;
    const float* cwt = g_CWT + h * DIMM * 128;

    float acc[16][4];
    #pragma unroll
    for (int i = 0; i < 16; i++)
        #pragma unroll
        for (int j = 0; j < 4; j++) acc[i][j] = 0.f;

    for (int kc = 0; kc < DIMM; kc += 64) {
        __syncthreads();
        // xs: 128 tokens x 64 k, convert to tf32
        for (int i = tid; i < 2048; i += 256) {
            int t = i >> 4, c4 = i & 15;
            float4 v = *(const float4*)(xp + (size_t)t * DIMM + kc + c4 * 4);
            v.x = tf32r(v.x); v.y = tf32r(v.y); v.z = tf32r(v.z); v.w = tf32r(v.w);
            *(float4*)(xs + t * 68 + c4 * 4) = v;
        }
        // ws: 64 k x 128 cols (already tf32)
        for (int i = tid; i < 2048; i += 256) {
            int kk = i >> 5, c4 = i & 31;
            *(float4*)(ws + kk * 136 + c4 * 4) = ((const float4*)(cwt + (kc + kk) * 128))[c4];
        }
        __syncthreads();
        #pragma unroll
        for (int ks = 0; ks < 8; ks++) {
            const int kb = ks * 8;
            uint32_t A0[2], A1[2], A2[2], A3[2];
            #pragma unroll
            for (int mi = 0; mi < 2; mi++) {
                int r = wm * 32 + mi * 16 + g;
                A0[mi] = FB(xs[r * 68 + kb + k4]);
                A1[mi] = FB(xs[(r + 8) * 68 + kb + k4]);
                A2[mi] = FB(xs[r * 68 + kb + k4 + 4]);
                A3[mi] = FB(xs[(r + 8) * 68 + kb + k4 + 4]);
            }
            #pragma unroll
            for (int ni = 0; ni < 8; ni++) {
                int c = wn * 64 + ni * 8 + g;
                uint32_t B0 = FB(ws[(kb + k4) * 136 + c]);
                uint32_t B1 = FB(ws[(kb + k4 + 4) * 136 + c]);
                mmat(acc[0 * 8 + ni], A0[0], A1[0], A2[0], A3[0], B0, B1);
                mmat(acc[1 * 8 + ni], A0[1], A1[1], A2[1], A3[1], B0, B1);
            }
        }
    }
    __syncthreads();

    // epilogue: bias + stage fx (tf32-rounded) and logits (fp32)
    float* fxs = sm;                 // [128][72]
    float* lgs = sm + 128 * 72;      // [128][72]
    {
        const float* cb = g_Cb + h * 128;
        float* dst = wn ? lgs : fxs;
        #pragma unroll
        for (int mi = 0; mi < 2; mi++) {
            int r0 = wm * 32 + mi * 16 + g;
            #pragma unroll
            for (int ni = 0; ni < 8; ni++) {
                int cl = ni * 8 + k4 * 2;
                float b0 = cb[wn * 64 + cl], b1 = cb[wn * 64 + cl + 1];
                float v00 = acc[mi * 8 + ni][0] + b0, v01 = acc[mi * 8 + ni][1] + b1;
                float v10 = acc[mi * 8 + ni][2] + b0, v11 = acc[mi * 8 + ni][3] + b1;
                if (!wn) { v00 = tf32r(v00); v01 = tf32r(v01); v10 = tf32r(v10); v11 = tf32r(v11); }
                dst[r0 * 72 + cl] = v00;
                dst[r0 * 72 + cl + 1] = v01;
                dst[(r0 + 8) * 72 + cl] = v10;
                dst[(r0 + 8) * 72 + cl + 1] = v11;
            }
        }
    }
    __syncthreads();

    // softmax: 128 tokens, 2 threads/token (32 values each)
    {
        int tok = tid >> 1, q2 = tid & 1;
        float* row = lgs + tok * 72 + q2 * 32;
        float m = -1e30f;
        #pragma unroll
        for (int s = 0; s < 32; s++) m = fmaxf(m, row[s]);
        m = fmaxf(m, __shfl_xor_sync(0xffffffffu, m, 1));
        float e[32];
        float sum = 0.f;
        #pragma unroll
        for (int s = 0; s < 32; s++) { e[s] = __expf(row[s] - m); sum += e[s]; }
        sum += __shfl_xor_sync(0xffffffffu, sum, 1);
        float inv = 1.f / sum;
        float* gw = g_w + (size_t)(b * NN + n0 + tok) * INNERR + h * 64 + q2 * 32;
        #pragma unroll
        for (int s = 0; s < 32; s++) { float v = tf32r(e[s] * inv); row[s] = v; }
        #pragma unroll
        for (int s4 = 0; s4 < 8; s4++) ((float4*)gw)[s4] = *(float4*)(row + s4 * 4);
    }
    __syncthreads();

    // slice_norm
    if (tid < 64) {
        float ns = 0.f;
        #pragma unroll 8
        for (int t = 0; t < 128; t++) ns += lgs[t * 72 + tid];
        atomicAdd(&g_norm[((size_t)b * HH + h) * 64 + tid], ns);
    }

    // tok[s][d] += sum_t w[t][s] * fx[t][d]   via mma: A[s][t]=lgs[t][s], B[t][d]=fxs[t][d]
    {
        float a2[4][4];
        #pragma unroll
        for (int i = 0; i < 4; i++)
            #pragma unroll
            for (int j = 0; j < 4; j++) a2[i][j] = 0.f;
        const int m0 = (w & 3) * 16;      // s base
        const int dh = (w >> 2) * 32;     // d base
        #pragma unroll
        for (int ks = 0; ks < 16; ks++) {
            const int kb = ks * 8;
            uint32_t A0 = FB(lgs[(kb + k4) * 72 + m0 + g]);
            uint32_t A1 = FB(lgs[(kb + k4) * 72 + m0 + g + 8]);
            uint32_t A2 = FB(lgs[(kb + k4 + 4) * 72 + m0 + g]);
            uint32_t A3 = FB(lgs[(kb + k4 + 4) * 72 + m0 + g + 8]);
            #pragma unroll
            for (int ni = 0; ni < 4; ni++) {
                int c = dh + ni * 8 + g;
                uint32_t B0 = FB(fxs[(kb + k4) * 72 + c]);
                uint32_t B1 = FB(fxs[(kb + k4 + 4) * 72 + c]);
                mmat(a2[ni], A0, A1, A2, A3, B0, B1);
            }
        }
        float* gt = g_tok + (size_t)((b * HH + h) * 64) * 64;
        #pragma unroll
        for (int ni = 0; ni < 4; ni++) {
            int s0 = m0 + g, c0 = dh + ni * 8 + k4 * 2;
            atomicAdd(gt + s0 * 64 + c0,        a2[ni][0]);
            atomicAdd(gt + s0 * 64 + c0 + 1,    a2[ni][1]);
            atomicAdd(gt + (s0 + 8) * 64 + c0,     a2[ni][2]);
            atomicAdd(gt + (s0 + 8) * 64 + c0 + 1, a2[ni][3]);
        }
    }
}

// ---------------- k2: tiny cross-slice attention, 4x4 register-blocked fp32 ----------------
// grid (H, B), block 256, dyn smem = 119296 B
__device__ __forceinline__ void gemm16(const float* __restrict__ A, int sa,
                                       const float* __restrict__ B /* stride 68, col-contig */,
                                       int tr, int tc, float o[4][4]) {
    #pragma unroll
    for (int i = 0; i < 4; i++)
        #pragma unroll
        for (int j = 0; j < 4; j++) o[i][j] = 0.f;
    #pragma unroll 4
    for (int e = 0; e < 64; e++) {
        float4 bv = *(const float4*)(B + e * 68 + tc * 4);
        #pragma unroll
        for (int i = 0; i < 4; i++) {
            float a = A[(tr * 4 + i) * sa + e];
            o[i][0] += a * bv.x; o[i][1] += a * bv.y;
            o[i][2] += a * bv.z; o[i][3] += a * bv.w;
        }
    }
}

__global__ void k2(const float* __restrict__ Wq, const float* __restrict__ Wk,
                   const float* __restrict__ Wv, const float* __restrict__ ascale_p,
                   const float* __restrict__ srs_p) {
    extern __shared__ float sm[];
    float* tokn = sm;                    // [64][65]
    float* kv   = sm + 4160;             // [64][65]
    float* qq   = sm + 8320;             // [64][65]
    float* kkt  = sm + 12480;            // [64][68]  (transposed k: [d][s])
    float* vv   = sm + 16832;            // [64][68]
    float* att  = sm + 21184;            // [64][65]
    float* wsm  = sm + 25344;            // [64][68]  (transposed weights: [e][d])
    float* nq   = sm + 29696;            // [64]
    float* nk   = nq + 64;               // [64]
    const int h = blockIdx.x, b = blockIdx.y;
    const int tid = threadIdx.x;
    const int tr = tid >> 4, tc = tid & 15;

    // normalized tok for this head + kv = mean over heads
    for (int i = tid; i < 4096; i += 256) {
        int s = i >> 6, d = i & 63;
        float accv = 0.f;
        #pragma unroll
        for (int hh = 0; hh < 8; hh++) {
            float nv = g_norm[(b * 8 + hh) * 64 + s] + 1e-5f;
            accv += g_tok[((b * 8 + hh) * 64 + s) * 64 + d] / nv;
        }
        kv[s * 65 + d] = accv * 0.125f;
        float nv = g_norm[(b * 8 + h) * 64 + s] + 1e-5f;
        tokn[s * 65 + d] = g_tok[((b * 8 + h) * 64 + s) * 64 + d] / nv;
    }
    __syncthreads();

    float o[4][4];

    // q = tokn @ Wq^T
    for (int i = tid; i < 4096; i += 256) { int e = i & 63, d = i >> 6; wsm[e * 68 + d] = Wq[d * 64 + e]; }
    __syncthreads();
    gemm16(tokn, 65, wsm, tr, tc, o);
    #pragma unroll
    for (int i = 0; i < 4; i++)
        #pragma unroll
        for (int j = 0; j < 4; j++) qq[(tr * 4 + i) * 65 + tc * 4 + j] = o[i][j];
    __syncthreads();

    // k = kv @ Wk^T, stored transposed
    for (int i = tid; i < 4096; i += 256) { int e = i & 63, d = i >> 6; wsm[e * 68 + d] = Wk[d * 64 + e]; }
    __syncthreads();
    gemm16(kv, 65, wsm, tr, tc, o);
    #pragma unroll
    for (int i = 0; i < 4; i++)
        #pragma unroll
        for (int j = 0; j < 4; j++) kkt[(tc * 4 + j) * 68 + tr * 4 + i] = o[i][j];
    __syncthreads();

    // v = kv @ Wv^T
    for (int i = tid; i < 4096; i += 256) { int e = i & 63, d = i >> 6; wsm[e * 68 + d] = Wv[d * 64 + e]; }
    __syncthreads();
    gemm16(kv, 65, wsm, tr, tc, o);
    #pragma unroll
    for (int i = 0; i < 4; i++)
        #pragma unroll
        for (int j = 0; j < 4; j++) vv[(tr * 4 + i) * 68 + tc * 4 + j] = o[i][j];
    __syncthreads();

    // norms
    if (tid < 64) {
        float s2 = 0.f;
        #pragma unroll 8
        for (int d = 0; d < 64; d++) { float v = qq[tid * 65 + d]; s2 += v * v; }
        nq[tid] = fmaxf(sqrtf(s2), 1e-12f);
    } else if (tid < 128) {
        int s = tid - 64;
        float s2 = 0.f;
        #pragma unroll 8
        for (int d = 0; d < 64; d++) { float v = kkt[d * 68 + s]; s2 += v * v; }
        nk[s] = fmaxf(sqrtf(s2), 1e-12f);
    }
    __syncthreads();

    // att logits = (qn . kn) * scale
    gemm16(qq, 65, kkt, tr, tc, o);
    {
        float asc = ascale_p[h];
        float rq[4], rk[4];
        #pragma unroll
        for (int i = 0; i < 4; i++) rq[i] = asc / nq[tr * 4 + i];
        #pragma unroll
        for (int j = 0; j < 4; j++) rk[j] = 1.f / nk[tc * 4 + j];
        #pragma unroll
        for (int i = 0; i < 4; i++)
            #pragma unroll
            for (int j = 0; j < 4; j++)
                att[(tr * 4 + i) * 65 + tc * 4 + j] = o[i][j] * rq[i] * rk[j];
    }
    __syncthreads();

    // softmax rows of att
    {
        int gg = tid >> 2, q4 = tid & 3;
        float* row = att + gg * 65;
        float m = -1e30f;
        #pragma unroll
        for (int s = 0; s < 16; s++) m = fmaxf(m, row[q4 * 16 + s]);
        m = fmaxf(m, __shfl_xor_sync(0xffffffffu, m, 1));
        m = fmaxf(m, __shfl_xor_sync(0xffffffffu, m, 2));
        float e[16];
        float sum = 0.f;
        #pragma unroll
        for (int s = 0; s < 16; s++) { e[s] = __expf(row[q4 * 16 + s] - m); sum += e[s]; }
        sum += __shfl_xor_sync(0xffffffffu, sum, 1);
        sum += __shfl_xor_sync(0xffffffffu, sum, 2);
        float inv = 1.f / sum;
        #pragma unroll
        for (int s = 0; s < 16; s++) row[q4 * 16 + s] = e[s] * inv;
    }
    __syncthreads();

    // out_tok = att @ v + sr * tokn
    gemm16(att, 65, vv, tr, tc, o);
    {
        float sr = srs_p[0];
        #pragma unroll
        for (int i = 0; i < 4; i++)
            #pragma unroll
            for (int j = 0; j < 4; j++) {
                int gg = tr * 4 + i, d = tc * 4 + j;
                g_ot[((b * 8 + h) * 64 + gg) * 64 + d] = o[i][j] + sr * tokn[gg * 65 + d];
            }
    }
}

// ---------------- M^T precompute (tf32-rounded) ----------------
__global__ void k2b(const float* __restrict__ Wout) {
    __shared__ float ots[16 * 64];
    const int b = blockIdx.y;
    const int j0 = blockIdx.x * 16;
    const int tid = threadIdx.x;
    for (int i = tid; i < 16 * 64; i += 256) {
        int jj = i >> 6, d = i & 63;
        int j = j0 + jj, h = j >> 6, s = j & 63;
        ots[jj * 64 + d] = g_ot[((b * 8 + h) * 64 + s) * 64 + d];
    }
    __syncthreads();
    int o = tid;
    int h = j0 >> 6;
    #pragma unroll 4
    for (int jj = 0; jj < 16; jj++) {
        float acc = 0.f;
        #pragma unroll 8
        for (int d = 0; d < 64; d++)
            acc += Wout[(size_t)o * INNERR + h * 64 + d] * ots[jj * 64 + d];
        g_MT[((size_t)b * INNERR + j0 + jj) * DIMM + o] = tf32r(acc);
    }
}

// ---------------- pass 2: y = w @ M^T + bout via tf32 mma ----------------
// grid (2, N/128, B), block 256, dyn smem = (128*68 + 64*136)*4 = 69632 B
__global__ __launch_bounds__(256, 2) void k3(const float* __restrict__ bout, float* __restrict__ out) {
    extern __shared__ float sm[];
    float* wt = sm;                 // [128][68]
    float* ms = sm + 128 * 68;      // [64][136]
    const int cb = blockIdx.x, nt = blockIdx.y, b = blockIdx.z;
    const int tid = threadIdx.x;
    const int lane = tid & 31, w = tid >> 5;
    const int wm = w & 3, wn = w >> 2;
    const int g = lane >> 2, k4 = lane & 3;
    const int n0 = nt * 128, col0 = cb * 128;
    const float* wp = g_w + (size_t)(b * NN + n0) * INNERR;
    const float* mp = g_MT + (size_t)b * INNERR * DIMM;

    float acc[16][4];
    #pragma unroll
    for (int i = 0; i < 16; i++)
        #pragma unroll
        for (int j = 0; j < 4; j++) acc[i][j] = 0.f;

    for (int kc = 0; kc < INNERR; kc += 64) {
        __syncthreads();
        for (int i = tid; i < 2048; i += 256) {
            int t = i >> 4, c4 = i & 15;
            *(float4*)(wt + t * 68 + c4 * 4) = *(const float4*)(wp + (size_t)t * INNERR + kc + c4 * 4);
        }
        for (int i = tid; i < 2048; i += 256) {
            int kk = i >> 5, c4 = i & 31;
            *(float4*)(ms + kk * 136 + c4 * 4) = *(const float4*)(mp + (size_t)(kc + kk) * DIMM + col0 + c4 * 4);
        }
        __syncthreads();
        #pragma unroll
        for (int ks = 0; ks < 8; ks++) {
            const int kb = ks * 8;
            uint32_t A0[2], A1[2], A2[2], A3[2];
            #pragma unroll
            for (int mi = 0; mi < 2; mi++) {
                int r = wm * 32 + mi * 16 + g;
                A0[mi] = FB(wt[r * 68 + kb + k4]);
                A1[mi] = FB(wt[(r + 8) * 68 + kb + k4]);
                A2[mi] = FB(wt[r * 68 + kb + k4 + 4]);
                A3[mi] = FB(wt[(r + 8) * 68 + kb + k4 + 4]);
            }
            #pragma unroll
            for (int ni = 0; ni < 8; ni++) {
                int c = wn * 64 + ni * 8 + g;
                uint32_t B0 = FB(ms[(kb + k4) * 136 + c]);
                uint32_t B1 = FB(ms[(kb + k4 + 4) * 136 + c]);
                mmat(acc[0 * 8 + ni], A0[0], A1[0], A2[0], A3[0], B0, B1);
                mmat(acc[1 * 8 + ni], A0[1], A1[1], A2[1], A3[1], B0, B1);
            }
        }
    }

    // epilogue: bias + store
    #pragma unroll
    for (int mi = 0; mi < 2; mi++) {
        #pragma unroll
        for (int ni = 0; ni < 8; ni++) {
            int cl = wn * 64 + ni * 8 + k4 * 2;
            float b0 = bout[col0 + cl], b1 = bout[col0 + cl + 1];
            int r0 = wm * 32 + mi * 16 + g;
            float* o0 = out + (size_t)(b * NN + n0 + r0) * DIMM + col0 + cl;
            float* o1 = out + (size_t)(b * NN + n0 + r0 + 8) * DIMM + col0 + cl;
            *(float2*)o0 = make_float2(acc[mi * 8 + ni][0] + b0, acc[mi * 8 + ni][1] + b1);
            *(float2*)o1 = make_float2(acc[mi * 8 + ni][2] + b0, acc[mi * 8 + ni][3] + b1);
        }
    }
}

// ---------------- launch ----------------
extern "C" void kernel_launch(void* const* d_in, const int* in_sizes, int n_in,
                              void* d_out, int out_size) {
    const float* x           = (const float*)d_in[0];
    const float* Wx          = (const float*)d_in[1];
    const float* bx          = (const float*)d_in[2];
    const float* Wfx         = (const float*)d_in[3];
    const float* bfx         = (const float*)d_in[4];
    const float* Wslice      = (const float*)d_in[5];
    const float* bslice      = (const float*)d_in[6];
    const float* temperature = (const float*)d_in[7];
    const float* Wq          = (const float*)d_in[8];
    const float* Wk          = (const float*)d_in[9];
    const float* Wv          = (const float*)d_in[10];
    const float* attn_scale  = (const float*)d_in[11];
    const float* srs         = (const float*)d_in[12];
    const float* Wout        = (const float*)d_in[13];
    const float* bout        = (const float*)d_in[14];
    float* out = (float*)d_out;

    const int K1S = 2 * 128 * 72 * (int)sizeof(float);            // 73728
    const int K2S = 29824 * (int)sizeof(float);                   // 119296
    const int K3S = (128 * 68 + 64 * 136) * (int)sizeof(float);   // 69632
    cudaFuncSetAttribute(k1, cudaFuncAttributeMaxDynamicSharedMemorySize, K1S);
    cudaFuncSetAttribute(k2, cudaFuncAttributeMaxDynamicSharedMemorySize, K2S);
    cudaFuncSetAttribute(k3, cudaFuncAttributeMaxDynamicSharedMemorySize, K3S);

    kz<<<512, 256>>>();
    k_prep<<<dim3(HH, DIMM), 128>>>(Wx, bx, Wfx, bfx, Wslice, bslice, temperature);
    k1<<<dim3(HH, NN / 128, BB), 256, K1S>>>(x);
    k2<<<dim3(HH, BB), 256, K2S>>>(Wq, Wk, Wv, attn_scale, srs);
    k2b<<<dim3(32, BB), 256>>>(Wout);
    k3<<<dim3(2, NN / 128, BB), 256, K3S>>>(bout, out);
}

// round 9
// speedup vs baseline: 2.7884x; 1.1814x over previous
#include <cuda_runtime.h>
#include <cuda_fp16.h>
#include <math.h>
#include <stdint.h>

#define BB 4
#define NN 16384
#define DIMM 256
#define HH 8
#define DD 64
#define SS 64
#define INNERR 512

// ---------------- device scratch ----------------
__device__ __half g_CWH[HH * 128 * DIMM];               // combined weight [h][col][k], half
__device__ float  g_Cb[HH * 128];                       // combined bias (fp32)
__device__ __half g_w[(size_t)BB * NN * INNERR];        // softmax slice weights [b][n][j], half
__device__ float  g_tok[BB * HH * SS * DD];             // accumulated tok (atomics)
__device__ float  g_norm[BB * HH * SS];                 // slice_norm (atomics)
__device__ float  g_ot[BB * HH * SS * DD];              // out_tok
__device__ __half g_M[BB * DIMM * INNERR];              // M [b][o][j], half

// ---------------- helpers ----------------
__device__ __forceinline__ float tf32r(float f) {
    uint32_t u;
    asm("cvt.rna.tf32.f32 %0, %1;" : "=r"(u) : "f"(f));
    return __uint_as_float(u);
}
__device__ __forceinline__ uint32_t FB(float f) { return __float_as_uint(f); }
__device__ __forceinline__ uint32_t ph2(float a, float b) {
    __half2 h = __floats2half2_rn(a, b);
    return *(uint32_t*)&h;
}

__device__ __forceinline__ void mmat(float* d, uint32_t a0, uint32_t a1, uint32_t a2, uint32_t a3,
                                     uint32_t b0, uint32_t b1) {
    asm volatile(
        "mma.sync.aligned.m16n8k8.row.col.f32.tf32.tf32.f32 "
        "{%0,%1,%2,%3},{%4,%5,%6,%7},{%8,%9},{%0,%1,%2,%3};"
        : "+f"(d[0]), "+f"(d[1]), "+f"(d[2]), "+f"(d[3])
        : "r"(a0), "r"(a1), "r"(a2), "r"(a3), "r"(b0), "r"(b1));
}

__device__ __forceinline__ void mmah(float* d, uint32_t a0, uint32_t a1, uint32_t a2, uint32_t a3,
                                     uint32_t b0, uint32_t b1) {
    asm volatile(
        "mma.sync.aligned.m16n8k16.row.col.f32.f16.f16.f32 "
        "{%0,%1,%2,%3},{%4,%5,%6,%7},{%8,%9},{%0,%1,%2,%3};"
        : "+f"(d[0]), "+f"(d[1]), "+f"(d[2]), "+f"(d[3])
        : "r"(a0), "r"(a1), "r"(a2), "r"(a3), "r"(b0), "r"(b1));
}

// ---------------- prep: combined weights (half, [h][col][k]) + zero accumulators ----------------
// grid (H, DIM), block 128
__global__ void k_prep(const float* __restrict__ Wx, const float* __restrict__ bx,
                       const float* __restrict__ Wfx, const float* __restrict__ bfx,
                       const float* __restrict__ Wslice, const float* __restrict__ bslice,
                       const float* __restrict__ temperature) {
    int h = blockIdx.x;
    int k = blockIdx.y;
    int col = threadIdx.x;

    // zero accumulators (covers all of g_tok / g_norm)
    int gid = (h * 256 + k) * 128 + col;
    if (gid < BB * HH * SS * DD) g_tok[gid] = 0.f;
    if (gid < BB * HH * SS) g_norm[gid] = 0.f;

    float invt = 1.f / fmaxf(temperature[h], 1e-4f);
    float v;
    if (col < 64) {
        v = Wfx[(h * 64 + col) * DIMM + k];
    } else {
        int s = col - 64;
        float acc = 0.f;
        #pragma unroll 8
        for (int d = 0; d < 64; d++)
            acc += Wslice[s * 64 + d] * Wx[(h * 64 + d) * DIMM + k];
        v = acc * invt;
    }
    g_CWH[(h * 128 + col) * DIMM + k] = __float2half_rn(v);
    if (k == 0) {
        float bv;
        if (col < 64) {
            bv = bfx[h * 64 + col];
        } else {
            int s = col - 64;
            float acc = bslice[s];
            #pragma unroll 8
            for (int d = 0; d < 64; d++) acc += Wslice[s * 64 + d] * bx[h * 64 + d];
            bv = acc * invt;
        }
        g_Cb[h * 128 + col] = bv;
    }
}

// ---------------- pass 1: fp16 mma GEMM + softmax + tok (tf32 mma) ----------------
// grid (H, N/128, B), block 256, dyn smem = 73728 B
// GEMM phase: xs half[128][72] + ws half[128][72] (36.9KB); epilogue: fxs f32[128][72] + lgs f32[128][72]
__global__ __launch_bounds__(256, 2) void k1(const float* __restrict__ x) {
    extern __shared__ float sm[];
    __half* xs = (__half*)sm;            // [128 tok][72 k] half
    __half* ws = xs + 128 * 72;          // [128 col][72 k] half
    const int h = blockIdx.x, nt = blockIdx.y, b = blockIdx.z;
    const int tid = threadIdx.x;
    const int lane = tid & 31, wid = tid >> 5;
    const int wm = wid & 3, wn = wid >> 2;   // m group (32 tokens), col half (64 cols)
    const int g = lane >> 2, k4 = lane & 3;
    const int n0 = nt * 128;

    const float* xp = x + (size_t)(b * NN + n0) * DIMM;
    const __half* cw = g_CWH + h * 128 * DIMM;   // [col][k]

    float acc[16][4];
    #pragma unroll
    for (int i = 0; i < 16; i++)
        #pragma unroll
        for (int j = 0; j < 4; j++) acc[i][j] = 0.f;

    uint32_t* xw = (uint32_t*)xs;

    for (int kc = 0; kc < DIMM; kc += 64) {
        __syncthreads();
        // xs: 128 tokens x 64 k, fp32 -> half
        for (int i = tid; i < 2048; i += 256) {
            int t = i >> 4, c4 = i & 15;
            float4 v = *(const float4*)(xp + (size_t)t * DIMM + kc + c4 * 4);
            xw[t * 36 + c4 * 2] = ph2(v.x, v.y);
            xw[t * 36 + c4 * 2 + 1] = ph2(v.z, v.w);
        }
        // ws: 128 cols x 64 k (already half, k-contiguous)
        for (int i = tid; i < 1024; i += 256) {
            int c = i >> 3, v8 = i & 7;
            ((uint4*)ws)[c * 9 + v8] = ((const uint4*)(cw + c * DIMM + kc))[v8];
        }
        __syncthreads();
        #pragma unroll
        for (int ks = 0; ks < 4; ks++) {
            const int kb = ks * 16;
            uint32_t A[2][4];
            #pragma unroll
            for (int mi = 0; mi < 2; mi++) {
                int r = wm * 32 + mi * 16 + g;
                const __half* x0 = xs + r * 72 + kb;
                const __half* x1 = xs + (r + 8) * 72 + kb;
                A[mi][0] = *(const uint32_t*)(x0 + 2 * k4);
                A[mi][1] = *(const uint32_t*)(x1 + 2 * k4);
                A[mi][2] = *(const uint32_t*)(x0 + 2 * k4 + 8);
                A[mi][3] = *(const uint32_t*)(x1 + 2 * k4 + 8);
            }
            #pragma unroll
            for (int ni = 0; ni < 8; ni++) {
                int c = wn * 64 + ni * 8 + g;
                const __half* bp = ws + c * 72 + kb;
                uint32_t B0 = *(const uint32_t*)(bp + 2 * k4);
                uint32_t B1 = *(const uint32_t*)(bp + 2 * k4 + 8);
                mmah(acc[0 * 8 + ni], A[0][0], A[0][1], A[0][2], A[0][3], B0, B1);
                mmah(acc[1 * 8 + ni], A[1][0], A[1][1], A[1][2], A[1][3], B0, B1);
            }
        }
    }
    __syncthreads();

    // epilogue: bias + stage fx (tf32-rounded fp32) and logits (fp32)
    float* fxs = sm;                 // [128][72]
    float* lgs = sm + 128 * 72;      // [128][72]
    {
        const float* cb = g_Cb + h * 128;
        float* dst = wn ? lgs : fxs;
        #pragma unroll
        for (int mi = 0; mi < 2; mi++) {
            int r0 = wm * 32 + mi * 16 + g;
            #pragma unroll
            for (int ni = 0; ni < 8; ni++) {
                int cl = ni * 8 + k4 * 2;
                float b0 = cb[wn * 64 + cl], b1 = cb[wn * 64 + cl + 1];
                float v00 = acc[mi * 8 + ni][0] + b0, v01 = acc[mi * 8 + ni][1] + b1;
                float v10 = acc[mi * 8 + ni][2] + b0, v11 = acc[mi * 8 + ni][3] + b1;
                if (!wn) { v00 = tf32r(v00); v01 = tf32r(v01); v10 = tf32r(v10); v11 = tf32r(v11); }
                dst[r0 * 72 + cl] = v00;
                dst[r0 * 72 + cl + 1] = v01;
                dst[(r0 + 8) * 72 + cl] = v10;
                dst[(r0 + 8) * 72 + cl + 1] = v11;
            }
        }
    }
    __syncthreads();

    // softmax: 128 tokens, 2 threads/token (32 values each); write g_w as half
    {
        int tok = tid >> 1, q2 = tid & 1;
        float* row = lgs + tok * 72 + q2 * 32;
        float m = -1e30f;
        #pragma unroll
        for (int s = 0; s < 32; s++) m = fmaxf(m, row[s]);
        m = fmaxf(m, __shfl_xor_sync(0xffffffffu, m, 1));
        float e[32];
        float sum = 0.f;
        #pragma unroll
        for (int s = 0; s < 32; s++) { e[s] = __expf(row[s] - m); sum += e[s]; }
        sum += __shfl_xor_sync(0xffffffffu, sum, 1);
        float inv = 1.f / sum;
        float v[32];
        #pragma unroll
        for (int s = 0; s < 32; s++) { v[s] = e[s] * inv; row[s] = tf32r(v[s]); }
        __half* gw = g_w + (size_t)(b * NN + n0 + tok) * INNERR + h * 64 + q2 * 32;
        uint4* gp = (uint4*)gw;
        gp[0] = make_uint4(ph2(v[0], v[1]), ph2(v[2], v[3]), ph2(v[4], v[5]), ph2(v[6], v[7]));
        gp[1] = make_uint4(ph2(v[8], v[9]), ph2(v[10], v[11]), ph2(v[12], v[13]), ph2(v[14], v[15]));
        gp[2] = make_uint4(ph2(v[16], v[17]), ph2(v[18], v[19]), ph2(v[20], v[21]), ph2(v[22], v[23]));
        gp[3] = make_uint4(ph2(v[24], v[25]), ph2(v[26], v[27]), ph2(v[28], v[29]), ph2(v[30], v[31]));
    }
    __syncthreads();

    // slice_norm
    if (tid < 64) {
        float ns = 0.f;
        #pragma unroll 8
        for (int t = 0; t < 128; t++) ns += lgs[t * 72 + tid];
        atomicAdd(&g_norm[((size_t)b * HH + h) * 64 + tid], ns);
    }

    // tok[s][d] += sum_t w[t][s] * fx[t][d]  (tf32 mma, fp32 smem)
    {
        float a2[4][4];
        #pragma unroll
        for (int i = 0; i < 4; i++)
            #pragma unroll
            for (int j = 0; j < 4; j++) a2[i][j] = 0.f;
        const int m0 = (wid & 3) * 16;      // s base
        const int dh = (wid >> 2) * 32;     // d base
        #pragma unroll
        for (int ks = 0; ks < 16; ks++) {
            const int kb = ks * 8;
            uint32_t A0 = FB(lgs[(kb + k4) * 72 + m0 + g]);
            uint32_t A1 = FB(lgs[(kb + k4) * 72 + m0 + g + 8]);
            uint32_t A2 = FB(lgs[(kb + k4 + 4) * 72 + m0 + g]);
            uint32_t A3 = FB(lgs[(kb + k4 + 4) * 72 + m0 + g + 8]);
            #pragma unroll
            for (int ni = 0; ni < 4; ni++) {
                int c = dh + ni * 8 + g;
                uint32_t B0 = FB(fxs[(kb + k4) * 72 + c]);
                uint32_t B1 = FB(fxs[(kb + k4 + 4) * 72 + c]);
                mmat(a2[ni], A0, A1, A2, A3, B0, B1);
            }
        }
        float* gt = g_tok + (size_t)((b * HH + h) * 64) * 64;
        #pragma unroll
        for (int ni = 0; ni < 4; ni++) {
            int s0 = m0 + g, c0 = dh + ni * 8 + k4 * 2;
            atomicAdd(gt + s0 * 64 + c0,           a2[ni][0]);
            atomicAdd(gt + s0 * 64 + c0 + 1,       a2[ni][1]);
            atomicAdd(gt + (s0 + 8) * 64 + c0,     a2[ni][2]);
            atomicAdd(gt + (s0 + 8) * 64 + c0 + 1, a2[ni][3]);
        }
    }
}

// ---------------- k2: tiny cross-slice attention, merged qkv, rcp/rsqrt ----------------
__device__ __forceinline__ void gemm16(const float* __restrict__ A, int sa,
                                       const float* __restrict__ B /* stride 68 */,
                                       int tr, int tc, float o[4][4]) {
    #pragma unroll
    for (int i = 0; i < 4; i++)
        #pragma unroll
        for (int j = 0; j < 4; j++) o[i][j] = 0.f;
    #pragma unroll 4
    for (int e = 0; e < 64; e++) {
        float4 bv = *(const float4*)(B + e * 68 + tc * 4);
        #pragma unroll
        for (int i = 0; i < 4; i++) {
            float a = A[(tr * 4 + i) * sa + e];
            o[i][0] += a * bv.x; o[i][1] += a * bv.y;
            o[i][2] += a * bv.z; o[i][3] += a * bv.w;
        }
    }
}

// grid (H, B), block 256, dyn smem = 156160 B
__global__ void k2(const float* __restrict__ Wq, const float* __restrict__ Wk,
                   const float* __restrict__ Wv, const float* __restrict__ ascale_p,
                   const float* __restrict__ srs_p) {
    extern __shared__ float sm[];
    float* rn   = sm;                    // [512]    1/(norm+eps) all heads
    float* tokn = sm + 512;              // [64][65]
    float* kv   = sm + 4672;             // [64][65]
    float* wq   = sm + 8832;             // [64][68] transposed [e][d]
    float* wk   = sm + 13184;            // [64][68]
    float* wv   = sm + 17536;            // [64][68]
    float* qq   = sm + 21888;            // [64][65]
    float* kkt  = sm + 26048;            // [64][68] transposed k: [d][s]
    float* vv   = sm + 30400;            // [64][68]
    float* att  = sm + 34752;            // [64][65]
    float* nqi  = sm + 38912;            // [64]
    float* nki  = sm + 38976;            // [64]
    const int h = blockIdx.x, b = blockIdx.y;
    const int tid = threadIdx.x;
    const int tr = tid >> 4, tc = tid & 15;

    // reciprocal norms + transposed weights
    for (int i = tid; i < 512; i += 256) rn[i] = __frcp_rn(g_norm[b * 512 + i] + 1e-5f);
    for (int i = tid; i < 4096; i += 256) {
        int e = i & 63, d = i >> 6;
        wq[e * 68 + d] = Wq[d * 64 + e];
        wk[e * 68 + d] = Wk[d * 64 + e];
        wv[e * 68 + d] = Wv[d * 64 + e];
    }
    __syncthreads();

    // normalized tok for this head + kv = mean over heads
    for (int i = tid; i < 4096; i += 256) {
        int s = i >> 6, d = i & 63;
        float accv = 0.f;
        #pragma unroll
        for (int hh = 0; hh < 8; hh++)
            accv += g_tok[((b * 8 + hh) * 64 + s) * 64 + d] * rn[hh * 64 + s];
        kv[s * 65 + d] = accv * 0.125f;
        tokn[s * 65 + d] = g_tok[((b * 8 + h) * 64 + s) * 64 + d] * rn[h * 64 + s];
    }
    __syncthreads();

    // merged q/k/v GEMMs (3x ILP in one pass)
    {
        float oq[4][4], ok[4][4], ov[4][4];
        #pragma unroll
        for (int i = 0; i < 4; i++)
            #pragma unroll
            for (int j = 0; j < 4; j++) { oq[i][j] = 0.f; ok[i][j] = 0.f; ov[i][j] = 0.f; }
        #pragma unroll 2
        for (int e = 0; e < 64; e++) {
            float4 bq = *(const float4*)(wq + e * 68 + tc * 4);
            float4 bk = *(const float4*)(wk + e * 68 + tc * 4);
            float4 bv = *(const float4*)(wv + e * 68 + tc * 4);
            #pragma unroll
            for (int i = 0; i < 4; i++) {
                float aq = tokn[(tr * 4 + i) * 65 + e];
                float ak = kv[(tr * 4 + i) * 65 + e];
                oq[i][0] += aq * bq.x; oq[i][1] += aq * bq.y; oq[i][2] += aq * bq.z; oq[i][3] += aq * bq.w;
                ok[i][0] += ak * bk.x; ok[i][1] += ak * bk.y; ok[i][2] += ak * bk.z; ok[i][3] += ak * bk.w;
                ov[i][0] += ak * bv.x; ov[i][1] += ak * bv.y; ov[i][2] += ak * bv.z; ov[i][3] += ak * bv.w;
            }
        }
        #pragma unroll
        for (int i = 0; i < 4; i++)
            #pragma unroll
            for (int j = 0; j < 4; j++) {
                qq[(tr * 4 + i) * 65 + tc * 4 + j]  = oq[i][j];
                kkt[(tc * 4 + j) * 68 + tr * 4 + i] = ok[i][j];
                vv[(tr * 4 + i) * 68 + tc * 4 + j]  = ov[i][j];
            }
    }
    __syncthreads();

    // inverse norms via rsqrt
    if (tid < 64) {
        float s2 = 0.f;
        #pragma unroll 8
        for (int d = 0; d < 64; d++) { float v = qq[tid * 65 + d]; s2 += v * v; }
        nqi[tid] = rsqrtf(fmaxf(s2, 1e-24f));
    } else if (tid < 128) {
        int s = tid - 64;
        float s2 = 0.f;
        #pragma unroll 8
        for (int d = 0; d < 64; d++) { float v = kkt[d * 68 + s]; s2 += v * v; }
        nki[s] = rsqrtf(fmaxf(s2, 1e-24f));
    }
    __syncthreads();

    float o[4][4];
    // att logits = (qn . kn) * scale
    gemm16(qq, 65, kkt, tr, tc, o);
    {
        float asc = ascale_p[h];
        float rq[4], rk[4];
        #pragma unroll
        for (int i = 0; i < 4; i++) rq[i] = asc * nqi[tr * 4 + i];
        #pragma unroll
        for (int j = 0; j < 4; j++) rk[j] = nki[tc * 4 + j];
        #pragma unroll
        for (int i = 0; i < 4; i++)
            #pragma unroll
            for (int j = 0; j < 4; j++)
                att[(tr * 4 + i) * 65 + tc * 4 + j] = o[i][j] * rq[i] * rk[j];
    }
    __syncthreads();

    // softmax rows of att
    {
        int gg = tid >> 2, q4 = tid & 3;
        float* row = att + gg * 65;
        float m = -1e30f;
        #pragma unroll
        for (int s = 0; s < 16; s++) m = fmaxf(m, row[q4 * 16 + s]);
        m = fmaxf(m, __shfl_xor_sync(0xffffffffu, m, 1));
        m = fmaxf(m, __shfl_xor_sync(0xffffffffu, m, 2));
        float e[16];
        float sum = 0.f;
        #pragma unroll
        for (int s = 0; s < 16; s++) { e[s] = __expf(row[q4 * 16 + s] - m); sum += e[s]; }
        sum += __shfl_xor_sync(0xffffffffu, sum, 1);
        sum += __shfl_xor_sync(0xffffffffu, sum, 2);
        float inv = 1.f / sum;
        #pragma unroll
        for (int s = 0; s < 16; s++) row[q4 * 16 + s] = e[s] * inv;
    }
    __syncthreads();

    // out_tok = att @ v + sr * tokn
    gemm16(att, 65, vv, tr, tc, o);
    {
        float sr = srs_p[0];
        #pragma unroll
        for (int i = 0; i < 4; i++)
            #pragma unroll
            for (int j = 0; j < 4; j++) {
                int gg = tr * 4 + i, d = tc * 4 + j;
                g_ot[((b * 8 + h) * 64 + gg) * 64 + d] = o[i][j] + sr * tokn[gg * 65 + d];
            }
    }
}

// ---------------- M precompute (half, [b][o][j]) ----------------
// grid (32, B), block 256
__global__ void k2b(const float* __restrict__ Wout) {
    __shared__ float ots[16 * 64];
    const int b = blockIdx.y;
    const int j0 = blockIdx.x * 16;
    const int tid = threadIdx.x;
    for (int i = tid; i < 16 * 64; i += 256) {
        int jj = i >> 6, d = i & 63;
        int j = j0 + jj, h = j >> 6, s = j & 63;
        ots[jj * 64 + d] = g_ot[((b * 8 + h) * 64 + s) * 64 + d];
    }
    __syncthreads();
    int o = tid;
    int h = j0 >> 6;
    float facc[16];
    #pragma unroll 4
    for (int jj = 0; jj < 16; jj++) {
        float acc = 0.f;
        #pragma unroll 8
        for (int d = 0; d < 64; d++)
            acc += Wout[(size_t)o * INNERR + h * 64 + d] * ots[jj * 64 + d];
        facc[jj] = acc;
    }
    __half2* mp = (__half2*)(g_M + ((size_t)b * DIMM + o) * INNERR + j0);
    #pragma unroll
    for (int p = 0; p < 8; p++) mp[p] = __floats2half2_rn(facc[2 * p], facc[2 * p + 1]);
}

// ---------------- pass 2: y = w @ M^T + bout via fp16 mma ----------------
// grid (2, N/128, B), block 256, dyn smem = 36864 B
__global__ __launch_bounds__(256, 2) void k3(const float* __restrict__ bout, float* __restrict__ out) {
    extern __shared__ float sm[];
    __half* wt = (__half*)sm;            // [128 tok][72 j] half
    __half* ms = wt + 128 * 72;          // [128 o][72 j] half
    const int cb = blockIdx.x, nt = blockIdx.y, b = blockIdx.z;
    const int tid = threadIdx.x;
    const int lane = tid & 31, wid = tid >> 5;
    const int wm = wid & 3, wn = wid >> 2;
    const int g = lane >> 2, k4 = lane & 3;
    const int n0 = nt * 128, col0 = cb * 128;
    const __half* wp = g_w + (size_t)(b * NN + n0) * INNERR;
    const __half* mp = g_M + (size_t)b * DIMM * INNERR;

    float acc[16][4];
    #pragma unroll
    for (int i = 0; i < 16; i++)
        #pragma unroll
        for (int j = 0; j < 4; j++) acc[i][j] = 0.f;

    for (int kc = 0; kc < INNERR; kc += 64) {
        __syncthreads();
        for (int i = tid; i < 1024; i += 256) {
            int t = i >> 3, v8 = i & 7;
            ((uint4*)wt)[t * 9 + v8] = ((const uint4*)(wp + (size_t)t * INNERR + kc))[v8];
        }
        for (int i = tid; i < 1024; i += 256) {
            int o = i >> 3, v8 = i & 7;
            ((uint4*)ms)[o * 9 + v8] = ((const uint4*)(mp + (size_t)(col0 + o) * INNERR + kc))[v8];
        }
        __syncthreads();
        #pragma unroll
        for (int ks = 0; ks < 4; ks++) {
            const int kb = ks * 16;
            uint32_t A[2][4];
            #pragma unroll
            for (int mi = 0; mi < 2; mi++) {
                int r = wm * 32 + mi * 16 + g;
                const __half* x0 = wt + r * 72 + kb;
                const __half* x1 = wt + (r + 8) * 72 + kb;
                A[mi][0] = *(const uint32_t*)(x0 + 2 * k4);
                A[mi][1] = *(const uint32_t*)(x1 + 2 * k4);
                A[mi][2] = *(const uint32_t*)(x0 + 2 * k4 + 8);
                A[mi][3] = *(const uint32_t*)(x1 + 2 * k4 + 8);
            }
            #pragma unroll
            for (int ni = 0; ni < 8; ni++) {
                int c = wn * 64 + ni * 8 + g;
                const __half* bp = ms + c * 72 + kb;
                uint32_t B0 = *(const uint32_t*)(bp + 2 * k4);
                uint32_t B1 = *(const uint32_t*)(bp + 2 * k4 + 8);
                mmah(acc[0 * 8 + ni], A[0][0], A[0][1], A[0][2], A[0][3], B0, B1);
                mmah(acc[1 * 8 + ni], A[1][0], A[1][1], A[1][2], A[1][3], B0, B1);
            }
        }
    }

    // epilogue: bias + store
    #pragma unroll
    for (int mi = 0; mi < 2; mi++) {
        #pragma unroll
        for (int ni = 0; ni < 8; ni++) {
            int cl = wn * 64 + ni * 8 + k4 * 2;
            float b0 = bout[col0 + cl], b1 = bout[col0 + cl + 1];
            int r0 = wm * 32 + mi * 16 + g;
            float* o0 = out + (size_t)(b * NN + n0 + r0) * DIMM + col0 + cl;
            float* o1 = out + (size_t)(b * NN + n0 + r0 + 8) * DIMM + col0 + cl;
            *(float2*)o0 = make_float2(acc[mi * 8 + ni][0] + b0, acc[mi * 8 + ni][1] + b1);
            *(float2*)o1 = make_float2(acc[mi * 8 + ni][2] + b0, acc[mi * 8 + ni][3] + b1);
        }
    }
}

// ---------------- launch ----------------
extern "C" void kernel_launch(void* const* d_in, const int* in_sizes, int n_in,
                              void* d_out, int out_size) {
    const float* x           = (const float*)d_in[0];
    const float* Wx          = (const float*)d_in[1];
    const float* bx          = (const float*)d_in[2];
    const float* Wfx         = (const float*)d_in[3];
    const float* bfx         = (const float*)d_in[4];
    const float* Wslice      = (const float*)d_in[5];
    const float* bslice      = (const float*)d_in[6];
    const float* temperature = (const float*)d_in[7];
    const float* Wq          = (const float*)d_in[8];
    const float* Wk          = (const float*)d_in[9];
    const float* Wv          = (const float*)d_in[10];
    const float* attn_scale  = (const float*)d_in[11];
    const float* srs         = (const float*)d_in[12];
    const float* Wout        = (const float*)d_in[13];
    const float* bout        = (const float*)d_in[14];
    float* out = (float*)d_out;

    const int K1S = 2 * 128 * 72 * (int)sizeof(float);   // 73728
    const int K2S = 39040 * (int)sizeof(float);          // 156160
    const int K3S = 2 * 128 * 72 * (int)sizeof(__half);  // 36864
    cudaFuncSetAttribute(k1, cudaFuncAttributeMaxDynamicSharedMemorySize, K1S);
    cudaFuncSetAttribute(k2, cudaFuncAttributeMaxDynamicSharedMemorySize, K2S);
    cudaFuncSetAttribute(k3, cudaFuncAttributeMaxDynamicSharedMemorySize, K3S);

    k_prep<<<dim3(HH, DIMM), 128>>>(Wx, bx, Wfx, bfx, Wslice, bslice, temperature);
    k1<<<dim3(HH, NN / 128, BB), 256, K1S>>>(x);
    k2<<<dim3(HH, BB), 256, K2S>>>(Wq, Wk, Wv, attn_scale, srs);
    k2b<<<dim3(32, BB), 256>>>(Wout);
    k3<<<dim3(2, NN / 128, BB), 256, K3S>>>(bout, out);
}

// round 10
// speedup vs baseline: 3.5067x; 1.2576x over previous
#include <cuda_runtime.h>
#include <cuda_fp16.h>
#include <math.h>
#include <stdint.h>

#define BB 4
#define NN 16384
#define DIMM 256
#define HH 8
#define DD 64
#define SS 64
#define INNERR 512

// ---------------- device scratch ----------------
__device__ __half g_CWH[HH * 128 * DIMM];               // combined weight [h][col][k], half
__device__ float  g_Cb[HH * 128];                       // combined bias (fp32)
__device__ __half g_w[(size_t)BB * NN * INNERR];        // softmax slice weights [b][n][j], half
__device__ float  g_tok[BB * HH * SS * DD];             // accumulated tok (atomics)
__device__ float  g_norm[BB * HH * SS];                 // slice_norm (atomics)
__device__ __half g_M[BB * DIMM * INNERR];              // M [b][o][j], half

// ---------------- helpers ----------------
__device__ __forceinline__ float tf32r(float f) {
    uint32_t u;
    asm("cvt.rna.tf32.f32 %0, %1;" : "=r"(u) : "f"(f));
    return __uint_as_float(u);
}
__device__ __forceinline__ uint32_t FB(float f) { return __float_as_uint(f); }
__device__ __forceinline__ uint32_t ph2(float a, float b) {
    __half2 h = __floats2half2_rn(a, b);
    return *(uint32_t*)&h;
}

__device__ __forceinline__ void mmat(float* d, uint32_t a0, uint32_t a1, uint32_t a2, uint32_t a3,
                                     uint32_t b0, uint32_t b1) {
    asm volatile(
        "mma.sync.aligned.m16n8k8.row.col.f32.tf32.tf32.f32 "
        "{%0,%1,%2,%3},{%4,%5,%6,%7},{%8,%9},{%0,%1,%2,%3};"
        : "+f"(d[0]), "+f"(d[1]), "+f"(d[2]), "+f"(d[3])
        : "r"(a0), "r"(a1), "r"(a2), "r"(a3), "r"(b0), "r"(b1));
}

__device__ __forceinline__ void mmah(float* d, uint32_t a0, uint32_t a1, uint32_t a2, uint32_t a3,
                                     uint32_t b0, uint32_t b1) {
    asm volatile(
        "mma.sync.aligned.m16n8k16.row.col.f32.f16.f16.f32 "
        "{%0,%1,%2,%3},{%4,%5,%6,%7},{%8,%9},{%0,%1,%2,%3};"
        : "+f"(d[0]), "+f"(d[1]), "+f"(d[2]), "+f"(d[3])
        : "r"(a0), "r"(a1), "r"(a2), "r"(a3), "r"(b0), "r"(b1));
}

// ---------------- prep: combined weights (half, [h][col][k]) + zero accumulators ----------------
// grid (H, DIM), block 128
__global__ void k_prep(const float* __restrict__ Wx, const float* __restrict__ bx,
                       const float* __restrict__ Wfx, const float* __restrict__ bfx,
                       const float* __restrict__ Wslice, const float* __restrict__ bslice,
                       const float* __restrict__ temperature) {
    int h = blockIdx.x;
    int k = blockIdx.y;
    int col = threadIdx.x;

    int gid = (h * 256 + k) * 128 + col;
    if (gid < BB * HH * SS * DD) g_tok[gid] = 0.f;
    if (gid < BB * HH * SS) g_norm[gid] = 0.f;

    float invt = 1.f / fmaxf(temperature[h], 1e-4f);
    float v;
    if (col < 64) {
        v = Wfx[(h * 64 + col) * DIMM + k];
    } else {
        int s = col - 64;
        float acc = 0.f;
        #pragma unroll 8
        for (int d = 0; d < 64; d++)
            acc += Wslice[s * 64 + d] * Wx[(h * 64 + d) * DIMM + k];
        v = acc * invt;
    }
    g_CWH[(h * 128 + col) * DIMM + k] = __float2half_rn(v);
    if (k == 0) {
        float bv;
        if (col < 64) {
            bv = bfx[h * 64 + col];
        } else {
            int s = col - 64;
            float acc = bslice[s];
            #pragma unroll 8
            for (int d = 0; d < 64; d++) acc += Wslice[s * 64 + d] * bx[h * 64 + d];
            bv = acc * invt;
        }
        g_Cb[h * 128 + col] = bv;
    }
}

// ---------------- pass 1: fp16 mma GEMM + softmax + tok (tf32 mma) ----------------
// grid (H, N/128, B), block 256, dyn smem = 73728 B
__global__ __launch_bounds__(256, 2) void k1(const float* __restrict__ x) {
    extern __shared__ float sm[];
    __half* xs = (__half*)sm;            // [128 tok][72 k] half
    __half* ws = xs + 128 * 72;          // [128 col][72 k] half
    const int h = blockIdx.x, nt = blockIdx.y, b = blockIdx.z;
    const int tid = threadIdx.x;
    const int lane = tid & 31, wid = tid >> 5;
    const int wm = wid & 3, wn = wid >> 2;
    const int g = lane >> 2, k4 = lane & 3;
    const int n0 = nt * 128;

    const float* xp = x + (size_t)(b * NN + n0) * DIMM;
    const __half* cw = g_CWH + h * 128 * DIMM;

    float acc[16][4];
    #pragma unroll
    for (int i = 0; i < 16; i++)
        #pragma unroll
        for (int j = 0; j < 4; j++) acc[i][j] = 0.f;

    uint32_t* xw = (uint32_t*)xs;

    for (int kc = 0; kc < DIMM; kc += 64) {
        __syncthreads();
        for (int i = tid; i < 2048; i += 256) {
            int t = i >> 4, c4 = i & 15;
            float4 v = *(const float4*)(xp + (size_t)t * DIMM + kc + c4 * 4);
            xw[t * 36 + c4 * 2] = ph2(v.x, v.y);
            xw[t * 36 + c4 * 2 + 1] = ph2(v.z, v.w);
        }
        for (int i = tid; i < 1024; i += 256) {
            int c = i >> 3, v8 = i & 7;
            ((uint4*)ws)[c * 9 + v8] = ((const uint4*)(cw + c * DIMM + kc))[v8];
        }
        __syncthreads();
        #pragma unroll
        for (int ks = 0; ks < 4; ks++) {
            const int kb = ks * 16;
            uint32_t A[2][4];
            #pragma unroll
            for (int mi = 0; mi < 2; mi++) {
                int r = wm * 32 + mi * 16 + g;
                const __half* x0 = xs + r * 72 + kb;
                const __half* x1 = xs + (r + 8) * 72 + kb;
                A[mi][0] = *(const uint32_t*)(x0 + 2 * k4);
                A[mi][1] = *(const uint32_t*)(x1 + 2 * k4);
                A[mi][2] = *(const uint32_t*)(x0 + 2 * k4 + 8);
                A[mi][3] = *(const uint32_t*)(x1 + 2 * k4 + 8);
            }
            #pragma unroll
            for (int ni = 0; ni < 8; ni++) {
                int c = wn * 64 + ni * 8 + g;
                const __half* bp = ws + c * 72 + kb;
                uint32_t B0 = *(const uint32_t*)(bp + 2 * k4);
                uint32_t B1 = *(const uint32_t*)(bp + 2 * k4 + 8);
                mmah(acc[0 * 8 + ni], A[0][0], A[0][1], A[0][2], A[0][3], B0, B1);
                mmah(acc[1 * 8 + ni], A[1][0], A[1][1], A[1][2], A[1][3], B0, B1);
            }
        }
    }
    __syncthreads();

    // epilogue: bias + stage fx (tf32-rounded fp32) and logits (fp32)
    float* fxs = sm;                 // [128][72]
    float* lgs = sm + 128 * 72;      // [128][72]
    {
        const float* cb = g_Cb + h * 128;
        float* dst = wn ? lgs : fxs;
        #pragma unroll
        for (int mi = 0; mi < 2; mi++) {
            int r0 = wm * 32 + mi * 16 + g;
            #pragma unroll
            for (int ni = 0; ni < 8; ni++) {
                int cl = ni * 8 + k4 * 2;
                float b0 = cb[wn * 64 + cl], b1 = cb[wn * 64 + cl + 1];
                float v00 = acc[mi * 8 + ni][0] + b0, v01 = acc[mi * 8 + ni][1] + b1;
                float v10 = acc[mi * 8 + ni][2] + b0, v11 = acc[mi * 8 + ni][3] + b1;
                if (!wn) { v00 = tf32r(v00); v01 = tf32r(v01); v10 = tf32r(v10); v11 = tf32r(v11); }
                dst[r0 * 72 + cl] = v00;
                dst[r0 * 72 + cl + 1] = v01;
                dst[(r0 + 8) * 72 + cl] = v10;
                dst[(r0 + 8) * 72 + cl + 1] = v11;
            }
        }
    }
    __syncthreads();

    // softmax: 128 tokens, 2 threads/token; write g_w as half
    {
        int tok = tid >> 1, q2 = tid & 1;
        float* row = lgs + tok * 72 + q2 * 32;
        float m = -1e30f;
        #pragma unroll
        for (int s = 0; s < 32; s++) m = fmaxf(m, row[s]);
        m = fmaxf(m, __shfl_xor_sync(0xffffffffu, m, 1));
        float e[32];
        float sum = 0.f;
        #pragma unroll
        for (int s = 0; s < 32; s++) { e[s] = __expf(row[s] - m); sum += e[s]; }
        sum += __shfl_xor_sync(0xffffffffu, sum, 1);
        float inv = 1.f / sum;
        float v[32];
        #pragma unroll
        for (int s = 0; s < 32; s++) { v[s] = e[s] * inv; row[s] = tf32r(v[s]); }
        __half* gw = g_w + (size_t)(b * NN + n0 + tok) * INNERR + h * 64 + q2 * 32;
        uint4* gp = (uint4*)gw;
        gp[0] = make_uint4(ph2(v[0], v[1]), ph2(v[2], v[3]), ph2(v[4], v[5]), ph2(v[6], v[7]));
        gp[1] = make_uint4(ph2(v[8], v[9]), ph2(v[10], v[11]), ph2(v[12], v[13]), ph2(v[14], v[15]));
        gp[2] = make_uint4(ph2(v[16], v[17]), ph2(v[18], v[19]), ph2(v[20], v[21]), ph2(v[22], v[23]));
        gp[3] = make_uint4(ph2(v[24], v[25]), ph2(v[26], v[27]), ph2(v[28], v[29]), ph2(v[30], v[31]));
    }
    __syncthreads();

    // slice_norm
    if (tid < 64) {
        float ns = 0.f;
        #pragma unroll 8
        for (int t = 0; t < 128; t++) ns += lgs[t * 72 + tid];
        atomicAdd(&g_norm[((size_t)b * HH + h) * 64 + tid], ns);
    }

    // tok[s][d] += sum_t w[t][s] * fx[t][d]  (tf32 mma)
    {
        float a2[4][4];
        #pragma unroll
        for (int i = 0; i < 4; i++)
            #pragma unroll
            for (int j = 0; j < 4; j++) a2[i][j] = 0.f;
        const int m0 = (wid & 3) * 16;
        const int dh = (wid >> 2) * 32;
        #pragma unroll
        for (int ks = 0; ks < 16; ks++) {
            const int kb = ks * 8;
            uint32_t A0 = FB(lgs[(kb + k4) * 72 + m0 + g]);
            uint32_t A1 = FB(lgs[(kb + k4) * 72 + m0 + g + 8]);
            uint32_t A2 = FB(lgs[(kb + k4 + 4) * 72 + m0 + g]);
            uint32_t A3 = FB(lgs[(kb + k4 + 4) * 72 + m0 + g + 8]);
            #pragma unroll
            for (int ni = 0; ni < 4; ni++) {
                int c = dh + ni * 8 + g;
                uint32_t B0 = FB(fxs[(kb + k4) * 72 + c]);
                uint32_t B1 = FB(fxs[(kb + k4 + 4) * 72 + c]);
                mmat(a2[ni], A0, A1, A2, A3, B0, B1);
            }
        }
        float* gt = g_tok + (size_t)((b * HH + h) * 64) * 64;
        #pragma unroll
        for (int ni = 0; ni < 4; ni++) {
            int s0 = m0 + g, c0 = dh + ni * 8 + k4 * 2;
            atomicAdd(gt + s0 * 64 + c0,           a2[ni][0]);
            atomicAdd(gt + s0 * 64 + c0 + 1,       a2[ni][1]);
            atomicAdd(gt + (s0 + 8) * 64 + c0,     a2[ni][2]);
            atomicAdd(gt + (s0 + 8) * 64 + c0 + 1, a2[ni][3]);
        }
    }
}

// ---------------- k2: cross-slice attention + fused M precompute ----------------
__device__ __forceinline__ void gemm16(const float* __restrict__ A, int sa,
                                       const float* __restrict__ B /* stride 68 */,
                                       int tr, int tc, float o[4][4]) {
    #pragma unroll
    for (int i = 0; i < 4; i++)
        #pragma unroll
        for (int j = 0; j < 4; j++) o[i][j] = 0.f;
    #pragma unroll 4
    for (int e = 0; e < 64; e++) {
        float4 bv = *(const float4*)(B + e * 68 + tc * 4);
        #pragma unroll
        for (int i = 0; i < 4; i++) {
            float a = A[(tr * 4 + i) * sa + e];
            o[i][0] += a * bv.x; o[i][1] += a * bv.y;
            o[i][2] += a * bv.z; o[i][3] += a * bv.w;
        }
    }
}

// grid (H, B), block 256, dyn smem = 156160 B
__global__ void k2(const float* __restrict__ Wq, const float* __restrict__ Wk,
                   const float* __restrict__ Wv, const float* __restrict__ ascale_p,
                   const float* __restrict__ srs_p, const float* __restrict__ Wout) {
    extern __shared__ float sm[];
    float* rn   = sm;                    // [512]
    float* tokn = sm + 512;              // [64][65]
    float* kv   = sm + 4672;             // [64][65]
    float* wq   = sm + 8832;             // [64][68] transposed [e][d]
    float* wk   = sm + 13184;            // [64][68]
    float* wv   = sm + 17536;            // [64][68]
    float* qq   = sm + 21888;            // [64][65]
    float* kkt  = sm + 26048;            // [64][68]
    float* vv   = sm + 30400;            // [64][68]
    float* att  = sm + 34752;            // [64][65]
    float* nqi  = sm + 38912;            // [64]
    float* nki  = sm + 38976;            // [64]
    const int h = blockIdx.x, b = blockIdx.y;
    const int tid = threadIdx.x;
    const int tr = tid >> 4, tc = tid & 15;

    for (int i = tid; i < 512; i += 256) rn[i] = __frcp_rn(g_norm[b * 512 + i] + 1e-5f);
    for (int i = tid; i < 4096; i += 256) {
        int e = i & 63, d = i >> 6;
        wq[e * 68 + d] = Wq[d * 64 + e];
        wk[e * 68 + d] = Wk[d * 64 + e];
        wv[e * 68 + d] = Wv[d * 64 + e];
    }
    __syncthreads();

    for (int i = tid; i < 4096; i += 256) {
        int s = i >> 6, d = i & 63;
        float accv = 0.f;
        #pragma unroll
        for (int hh = 0; hh < 8; hh++)
            accv += g_tok[((b * 8 + hh) * 64 + s) * 64 + d] * rn[hh * 64 + s];
        kv[s * 65 + d] = accv * 0.125f;
        tokn[s * 65 + d] = g_tok[((b * 8 + h) * 64 + s) * 64 + d] * rn[h * 64 + s];
    }
    __syncthreads();

    // merged q/k/v GEMMs
    {
        float oq[4][4], ok[4][4], ov[4][4];
        #pragma unroll
        for (int i = 0; i < 4; i++)
            #pragma unroll
            for (int j = 0; j < 4; j++) { oq[i][j] = 0.f; ok[i][j] = 0.f; ov[i][j] = 0.f; }
        #pragma unroll 2
        for (int e = 0; e < 64; e++) {
            float4 bq = *(const float4*)(wq + e * 68 + tc * 4);
            float4 bk = *(const float4*)(wk + e * 68 + tc * 4);
            float4 bv = *(const float4*)(wv + e * 68 + tc * 4);
            #pragma unroll
            for (int i = 0; i < 4; i++) {
                float aq = tokn[(tr * 4 + i) * 65 + e];
                float ak = kv[(tr * 4 + i) * 65 + e];
                oq[i][0] += aq * bq.x; oq[i][1] += aq * bq.y; oq[i][2] += aq * bq.z; oq[i][3] += aq * bq.w;
                ok[i][0] += ak * bk.x; ok[i][1] += ak * bk.y; ok[i][2] += ak * bk.z; ok[i][3] += ak * bk.w;
                ov[i][0] += ak * bv.x; ov[i][1] += ak * bv.y; ov[i][2] += ak * bv.z; ov[i][3] += ak * bv.w;
            }
        }
        #pragma unroll
        for (int i = 0; i < 4; i++)
            #pragma unroll
            for (int j = 0; j < 4; j++) {
                qq[(tr * 4 + i) * 65 + tc * 4 + j]  = oq[i][j];
                kkt[(tc * 4 + j) * 68 + tr * 4 + i] = ok[i][j];
                vv[(tr * 4 + i) * 68 + tc * 4 + j]  = ov[i][j];
            }
    }
    __syncthreads();

    if (tid < 64) {
        float s2 = 0.f;
        #pragma unroll 8
        for (int d = 0; d < 64; d++) { float v = qq[tid * 65 + d]; s2 += v * v; }
        nqi[tid] = rsqrtf(fmaxf(s2, 1e-24f));
    } else if (tid < 128) {
        int s = tid - 64;
        float s2 = 0.f;
        #pragma unroll 8
        for (int d = 0; d < 64; d++) { float v = kkt[d * 68 + s]; s2 += v * v; }
        nki[s] = rsqrtf(fmaxf(s2, 1e-24f));
    }
    __syncthreads();

    float o[4][4];
    gemm16(qq, 65, kkt, tr, tc, o);
    {
        float asc = ascale_p[h];
        float rq[4], rk[4];
        #pragma unroll
        for (int i = 0; i < 4; i++) rq[i] = asc * nqi[tr * 4 + i];
        #pragma unroll
        for (int j = 0; j < 4; j++) rk[j] = nki[tc * 4 + j];
        #pragma unroll
        for (int i = 0; i < 4; i++)
            #pragma unroll
            for (int j = 0; j < 4; j++)
                att[(tr * 4 + i) * 65 + tc * 4 + j] = o[i][j] * rq[i] * rk[j];
    }
    __syncthreads();

    // softmax rows of att
    {
        int gg = tid >> 2, q4 = tid & 3;
        float* row = att + gg * 65;
        float m = -1e30f;
        #pragma unroll
        for (int s = 0; s < 16; s++) m = fmaxf(m, row[q4 * 16 + s]);
        m = fmaxf(m, __shfl_xor_sync(0xffffffffu, m, 1));
        m = fmaxf(m, __shfl_xor_sync(0xffffffffu, m, 2));
        float e[16];
        float sum = 0.f;
        #pragma unroll
        for (int s = 0; s < 16; s++) { e[s] = __expf(row[q4 * 16 + s] - m); sum += e[s]; }
        sum += __shfl_xor_sync(0xffffffffu, sum, 1);
        sum += __shfl_xor_sync(0xffffffffu, sum, 2);
        float inv = 1.f / sum;
        #pragma unroll
        for (int s = 0; s < 16; s++) row[q4 * 16 + s] = e[s] * inv;
    }
    __syncthreads();

    // out_tok = att @ v + sr * tokn  -> store TRANSPOSED into ots_t[d][s] (reuse qq/kkt region)
    gemm16(att, 65, vv, tr, tc, o);
    float* ots_t = qq;   // [64 d][68] (qq+kkt region is dead; 64*68=4352 fits)
    {
        float sr = srs_p[0];
        #pragma unroll
        for (int i = 0; i < 4; i++)
            #pragma unroll
            for (int j = 0; j < 4; j++) {
                int gg = tr * 4 + i, d = tc * 4 + j;
                ots_t[d * 68 + gg] = o[i][j] + sr * tokn[gg * 65 + d];
            }
    }
    __syncthreads();

    // ---- fused M precompute: M[b][o][h*64+s] = sum_d Wout[o][h*64+d] * out_tok[s][d] ----
    // stage Wout slice coalesced: wos[o][d], stride 68 (reuses rn/tokn/kv/wq/wk region)
    float* wos = sm;     // [256][68] = 17408 floats, ends before wv region use? wv dead too.
    for (int i = tid; i < 16384; i += 256) {
        int oo = i >> 6, d = i & 63;
        wos[oo * 68 + d] = Wout[(size_t)oo * INNERR + h * 64 + d];
    }
    __syncthreads();

    {
        const int tcs = tid & 3;        // s block of 16
        const int tro = tid >> 2;       // o block of 4 (64 values * 4 = 256)
        float accm[4][16];
        #pragma unroll
        for (int i = 0; i < 4; i++)
            #pragma unroll
            for (int j = 0; j < 16; j++) accm[i][j] = 0.f;
        #pragma unroll 2
        for (int d = 0; d < 64; d++) {
            float4 s0 = *(const float4*)(ots_t + d * 68 + tcs * 16);
            float4 s1 = *(const float4*)(ots_t + d * 68 + tcs * 16 + 4);
            float4 s2 = *(const float4*)(ots_t + d * 68 + tcs * 16 + 8);
            float4 s3 = *(const float4*)(ots_t + d * 68 + tcs * 16 + 12);
            #pragma unroll
            for (int i = 0; i < 4; i++) {
                float a = wos[(tro * 4 + i) * 68 + d];
                accm[i][0]  += a * s0.x; accm[i][1]  += a * s0.y; accm[i][2]  += a * s0.z; accm[i][3]  += a * s0.w;
                accm[i][4]  += a * s1.x; accm[i][5]  += a * s1.y; accm[i][6]  += a * s1.z; accm[i][7]  += a * s1.w;
                accm[i][8]  += a * s2.x; accm[i][9]  += a * s2.y; accm[i][10] += a * s2.z; accm[i][11] += a * s2.w;
                accm[i][12] += a * s3.x; accm[i][13] += a * s3.y; accm[i][14] += a * s3.z; accm[i][15] += a * s3.w;
            }
        }
        #pragma unroll
        for (int i = 0; i < 4; i++) {
            int oo = tro * 4 + i;
            __half* mp = g_M + ((size_t)(b * DIMM + oo)) * INNERR + h * 64 + tcs * 16;
            uint4 p0, p1;
            p0.x = ph2(accm[i][0], accm[i][1]);   p0.y = ph2(accm[i][2], accm[i][3]);
            p0.z = ph2(accm[i][4], accm[i][5]);   p0.w = ph2(accm[i][6], accm[i][7]);
            p1.x = ph2(accm[i][8], accm[i][9]);   p1.y = ph2(accm[i][10], accm[i][11]);
            p1.z = ph2(accm[i][12], accm[i][13]); p1.w = ph2(accm[i][14], accm[i][15]);
            ((uint4*)mp)[0] = p0;
            ((uint4*)mp)[1] = p1;
        }
    }
}

// ---------------- pass 2: y = w @ M^T + bout via fp16 mma ----------------
// grid (2, N/128, B), block 256, dyn smem = 36864 B
__global__ __launch_bounds__(256, 2) void k3(const float* __restrict__ bout, float* __restrict__ out) {
    extern __shared__ float sm[];
    __half* wt = (__half*)sm;            // [128 tok][72 j] half
    __half* ms = wt + 128 * 72;          // [128 o][72 j] half
    const int cb = blockIdx.x, nt = blockIdx.y, b = blockIdx.z;
    const int tid = threadIdx.x;
    const int lane = tid & 31, wid = tid >> 5;
    const int wm = wid & 3, wn = wid >> 2;
    const int g = lane >> 2, k4 = lane & 3;
    const int n0 = nt * 128, col0 = cb * 128;
    const __half* wp = g_w + (size_t)(b * NN + n0) * INNERR;
    const __half* mp = g_M + (size_t)b * DIMM * INNERR;

    float acc[16][4];
    #pragma unroll
    for (int i = 0; i < 16; i++)
        #pragma unroll
        for (int j = 0; j < 4; j++) acc[i][j] = 0.f;

    for (int kc = 0; kc < INNERR; kc += 64) {
        __syncthreads();
        for (int i = tid; i < 1024; i += 256) {
            int t = i >> 3, v8 = i & 7;
            ((uint4*)wt)[t * 9 + v8] = ((const uint4*)(wp + (size_t)t * INNERR + kc))[v8];
        }
        for (int i = tid; i < 1024; i += 256) {
            int o = i >> 3, v8 = i & 7;
            ((uint4*)ms)[o * 9 + v8] = ((const uint4*)(mp + (size_t)(col0 + o) * INNERR + kc))[v8];
        }
        __syncthreads();
        #pragma unroll
        for (int ks = 0; ks < 4; ks++) {
            const int kb = ks * 16;
            uint32_t A[2][4];
            #pragma unroll
            for (int mi = 0; mi < 2; mi++) {
                int r = wm * 32 + mi * 16 + g;
                const __half* x0 = wt + r * 72 + kb;
                const __half* x1 = wt + (r + 8) * 72 + kb;
                A[mi][0] = *(const uint32_t*)(x0 + 2 * k4);
                A[mi][1] = *(const uint32_t*)(x1 + 2 * k4);
                A[mi][2] = *(const uint32_t*)(x0 + 2 * k4 + 8);
                A[mi][3] = *(const uint32_t*)(x1 + 2 * k4 + 8);
            }
            #pragma unroll
            for (int ni = 0; ni < 8; ni++) {
                int c = wn * 64 + ni * 8 + g;
                const __half* bp = ms + c * 72 + kb;
                uint32_t B0 = *(const uint32_t*)(bp + 2 * k4);
                uint32_t B1 = *(const uint32_t*)(bp + 2 * k4 + 8);
                mmah(acc[0 * 8 + ni], A[0][0], A[0][1], A[0][2], A[0][3], B0, B1);
                mmah(acc[1 * 8 + ni], A[1][0], A[1][1], A[1][2], A[1][3], B0, B1);
            }
        }
    }

    #pragma unroll
    for (int mi = 0; mi < 2; mi++) {
        #pragma unroll
        for (int ni = 0; ni < 8; ni++) {
            int cl = wn * 64 + ni * 8 + k4 * 2;
            float b0 = bout[col0 + cl], b1 = bout[col0 + cl + 1];
            int r0 = wm * 32 + mi * 16 + g;
            float* o0 = out + (size_t)(b * NN + n0 + r0) * DIMM + col0 + cl;
            float* o1 = out + (size_t)(b * NN + n0 + r0 + 8) * DIMM + col0 + cl;
            *(float2*)o0 = make_float2(acc[mi * 8 + ni][0] + b0, acc[mi * 8 + ni][1] + b1);
            *(float2*)o1 = make_float2(acc[mi * 8 + ni][2] + b0, acc[mi * 8 + ni][3] + b1);
        }
    }
}

// ---------------- launch ----------------
extern "C" void kernel_launch(void* const* d_in, const int* in_sizes, int n_in,
                              void* d_out, int out_size) {
    const float* x           = (const float*)d_in[0];
    const float* Wx          = (const float*)d_in[1];
    const float* bx          = (const float*)d_in[2];
    const float* Wfx         = (const float*)d_in[3];
    const float* bfx         = (const float*)d_in[4];
    const float* Wslice      = (const float*)d_in[5];
    const float* bslice      = (const float*)d_in[6];
    const float* temperature = (const float*)d_in[7];
    const float* Wq          = (const float*)d_in[8];
    const float* Wk          = (const float*)d_in[9];
    const float* Wv          = (const float*)d_in[10];
    const float* attn_scale  = (const float*)d_in[11];
    const float* srs         = (const float*)d_in[12];
    const float* Wout        = (const float*)d_in[13];
    const float* bout        = (const float*)d_in[14];
    float* out = (float*)d_out;

    const int K1S = 2 * 128 * 72 * (int)sizeof(float);   // 73728
    const int K2S = 39040 * (int)sizeof(float);          // 156160
    const int K3S = 2 * 128 * 72 * (int)sizeof(__half);  // 36864
    cudaFuncSetAttribute(k1, cudaFuncAttributeMaxDynamicSharedMemorySize, K1S);
    cudaFuncSetAttribute(k2, cudaFuncAttributeMaxDynamicSharedMemorySize, K2S);
    cudaFuncSetAttribute(k3, cudaFuncAttributeMaxDynamicSharedMemorySize, K3S);

    k_prep<<<dim3(HH, DIMM), 128>>>(Wx, bx, Wfx, bfx, Wslice, bslice, temperature);
    k1<<<dim3(HH, NN / 128, BB), 256, K1S>>>(x);
    k2<<<dim3(HH, BB), 256, K2S>>>(Wq, Wk, Wv, attn_scale, srs, Wout);
    k3<<<dim3(2, NN / 128, BB), 256, K3S>>>(bout, out);
}

// round 11
// speedup vs baseline: 4.8078x; 1.3710x over previous
#include <cuda_runtime.h>
#include <cuda_fp16.h>
#include <math.h>
#include <stdint.h>

#define BB 4
#define NN 16384
#define DIMM 256
#define HH 8
#define DD 64
#define SS 64
#define INNERR 512

// ---------------- device scratch ----------------
__device__ __half g_xh[(size_t)BB * NN * DIMM];         // x in half
__device__ __half g_CWH[HH * 128 * DIMM];               // combined weight [h][col][k], half
__device__ float  g_Cb[HH * 128];                       // combined bias (fp32)
__device__ __half g_w[(size_t)BB * NN * INNERR];        // softmax slice weights [b][n][j], half
__device__ float  g_tok[BB * HH * SS * DD];             // accumulated tok (atomics)
__device__ float  g_norm[BB * HH * SS];                 // slice_norm (atomics)
__device__ __half g_M[BB * DIMM * INNERR];              // M [b][o][j], half

// ---------------- helpers ----------------
__device__ __forceinline__ float tf32r(float f) {
    uint32_t u;
    asm("cvt.rna.tf32.f32 %0, %1;" : "=r"(u) : "f"(f));
    return __uint_as_float(u);
}
__device__ __forceinline__ uint32_t FB(float f) { return __float_as_uint(f); }
__device__ __forceinline__ uint32_t ph2(float a, float b) {
    __half2 h = __floats2half2_rn(a, b);
    return *(uint32_t*)&h;
}
__device__ __forceinline__ void cpa16(void* s, const void* g) {
    uint32_t sa = (uint32_t)__cvta_generic_to_shared(s);
    asm volatile("cp.async.cg.shared.global [%0], [%1], 16;\n" :: "r"(sa), "l"(g));
}
#define CPA_COMMIT asm volatile("cp.async.commit_group;\n" ::: "memory")
#define CPA_WAIT1  asm volatile("cp.async.wait_group 1;\n" ::: "memory")
#define CPA_WAIT0  asm volatile("cp.async.wait_group 0;\n" ::: "memory")

__device__ __forceinline__ void mmat(float* d, uint32_t a0, uint32_t a1, uint32_t a2, uint32_t a3,
                                     uint32_t b0, uint32_t b1) {
    asm volatile(
        "mma.sync.aligned.m16n8k8.row.col.f32.tf32.tf32.f32 "
        "{%0,%1,%2,%3},{%4,%5,%6,%7},{%8,%9},{%0,%1,%2,%3};"
        : "+f"(d[0]), "+f"(d[1]), "+f"(d[2]), "+f"(d[3])
        : "r"(a0), "r"(a1), "r"(a2), "r"(a3), "r"(b0), "r"(b1));
}

__device__ __forceinline__ void mmah(float* d, uint32_t a0, uint32_t a1, uint32_t a2, uint32_t a3,
                                     uint32_t b0, uint32_t b1) {
    asm volatile(
        "mma.sync.aligned.m16n8k16.row.col.f32.f16.f16.f32 "
        "{%0,%1,%2,%3},{%4,%5,%6,%7},{%8,%9},{%0,%1,%2,%3};"
        : "+f"(d[0]), "+f"(d[1]), "+f"(d[2]), "+f"(d[3])
        : "r"(a0), "r"(a1), "r"(a2), "r"(a3), "r"(b0), "r"(b1));
}

// ---------------- x -> half ----------------
// grid 8192, block 256: 8 floats / thread
__global__ void k_conv(const float* __restrict__ x) {
    size_t i = ((size_t)blockIdx.x * 256 + threadIdx.x) * 8;
    float4 a = *(const float4*)(x + i);
    float4 b = *(const float4*)(x + i + 4);
    uint4 p;
    p.x = ph2(a.x, a.y); p.y = ph2(a.z, a.w);
    p.z = ph2(b.x, b.y); p.w = ph2(b.z, b.w);
    *(uint4*)(g_xh + i) = p;
}

// ---------------- prep: combined weights (half, [h][col][k]) + zero accumulators ----------------
// grid (H, DIM), block 128
__global__ void k_prep(const float* __restrict__ Wx, const float* __restrict__ bx,
                       const float* __restrict__ Wfx, const float* __restrict__ bfx,
                       const float* __restrict__ Wslice, const float* __restrict__ bslice,
                       const float* __restrict__ temperature) {
    int h = blockIdx.x;
    int k = blockIdx.y;
    int col = threadIdx.x;

    int gid = (h * 256 + k) * 128 + col;
    if (gid < BB * HH * SS * DD) g_tok[gid] = 0.f;
    if (gid < BB * HH * SS) g_norm[gid] = 0.f;

    float invt = 1.f / fmaxf(temperature[h], 1e-4f);
    float v;
    if (col < 64) {
        v = Wfx[(h * 64 + col) * DIMM + k];
    } else {
        int s = col - 64;
        float acc = 0.f;
        #pragma unroll 8
        for (int d = 0; d < 64; d++)
            acc += Wslice[s * 64 + d] * Wx[(h * 64 + d) * DIMM + k];
        v = acc * invt;
    }
    g_CWH[(h * 128 + col) * DIMM + k] = __float2half_rn(v);
    if (k == 0) {
        float bv;
        if (col < 64) {
            bv = bfx[h * 64 + col];
        } else {
            int s = col - 64;
            float acc = bslice[s];
            #pragma unroll 8
            for (int d = 0; d < 64; d++) acc += Wslice[s * 64 + d] * bx[h * 64 + d];
            bv = acc * invt;
        }
        g_Cb[h * 128 + col] = bv;
    }
}

// ---------------- pass 1: pipelined fp16 mma GEMM + softmax + tok (tf32 mma) ----------------
// grid (H, N/128, B), block 256, dyn smem = 73728 B
// GEMM: 2 stages x (xs half[128][72] + ws half[128][72]); epilogue reuses as fxs/lgs f32[128][72]
__global__ __launch_bounds__(256, 2) void k1() {
    extern __shared__ float sm[];
    __half* base = (__half*)sm;
    const int h = blockIdx.x, nt = blockIdx.y, b = blockIdx.z;
    const int tid = threadIdx.x;
    const int lane = tid & 31, wid = tid >> 5;
    const int wm = wid & 3, wn = wid >> 2;
    const int g = lane >> 2, k4 = lane & 3;
    const int n0 = nt * 128;

    const __half* xh = g_xh + (size_t)(b * NN + n0) * DIMM;
    const __half* cw = g_CWH + h * 128 * DIMM;

    float acc[16][4];
    #pragma unroll
    for (int i = 0; i < 16; i++)
        #pragma unroll
        for (int j = 0; j < 4; j++) acc[i][j] = 0.f;

    // issue stage for chunk c
    auto issue = [&](int c) {
        __half* xs = base + (c & 1) * 18432;
        __half* ws = xs + 9216;
        int kc = c * 64;
        for (int i = tid; i < 1024; i += 256) {
            int t = i >> 3, v8 = i & 7;
            cpa16(xs + t * 72 + v8 * 8, xh + (size_t)t * DIMM + kc + v8 * 8);
            cpa16(ws + t * 72 + v8 * 8, cw + (size_t)t * DIMM + kc + v8 * 8);
        }
        CPA_COMMIT;
    };

    issue(0);
    for (int c = 0; c < 4; c++) {
        if (c + 1 < 4) { issue(c + 1); CPA_WAIT1; } else { CPA_WAIT0; }
        __syncthreads();
        __half* xs = base + (c & 1) * 18432;
        __half* ws = xs + 9216;
        #pragma unroll
        for (int ks = 0; ks < 4; ks++) {
            const int kb = ks * 16;
            uint32_t A[2][4];
            #pragma unroll
            for (int mi = 0; mi < 2; mi++) {
                int r = wm * 32 + mi * 16 + g;
                const __half* x0 = xs + r * 72 + kb;
                const __half* x1 = xs + (r + 8) * 72 + kb;
                A[mi][0] = *(const uint32_t*)(x0 + 2 * k4);
                A[mi][1] = *(const uint32_t*)(x1 + 2 * k4);
                A[mi][2] = *(const uint32_t*)(x0 + 2 * k4 + 8);
                A[mi][3] = *(const uint32_t*)(x1 + 2 * k4 + 8);
            }
            #pragma unroll
            for (int ni = 0; ni < 8; ni++) {
                int cc = wn * 64 + ni * 8 + g;
                const __half* bp = ws + cc * 72 + kb;
                uint32_t B0 = *(const uint32_t*)(bp + 2 * k4);
                uint32_t B1 = *(const uint32_t*)(bp + 2 * k4 + 8);
                mmah(acc[0 * 8 + ni], A[0][0], A[0][1], A[0][2], A[0][3], B0, B1);
                mmah(acc[1 * 8 + ni], A[1][0], A[1][1], A[1][2], A[1][3], B0, B1);
            }
        }
        __syncthreads();
    }

    // epilogue: bias + stage fx (tf32-rounded fp32) and logits (fp32)
    float* fxs = sm;                 // [128][72]
    float* lgs = sm + 128 * 72;      // [128][72]
    {
        const float* cb = g_Cb + h * 128;
        float* dst = wn ? lgs : fxs;
        #pragma unroll
        for (int mi = 0; mi < 2; mi++) {
            int r0 = wm * 32 + mi * 16 + g;
            #pragma unroll
            for (int ni = 0; ni < 8; ni++) {
                int cl = ni * 8 + k4 * 2;
                float b0 = cb[wn * 64 + cl], b1 = cb[wn * 64 + cl + 1];
                float v00 = acc[mi * 8 + ni][0] + b0, v01 = acc[mi * 8 + ni][1] + b1;
                float v10 = acc[mi * 8 + ni][2] + b0, v11 = acc[mi * 8 + ni][3] + b1;
                if (!wn) { v00 = tf32r(v00); v01 = tf32r(v01); v10 = tf32r(v10); v11 = tf32r(v11); }
                dst[r0 * 72 + cl] = v00;
                dst[r0 * 72 + cl + 1] = v01;
                dst[(r0 + 8) * 72 + cl] = v10;
                dst[(r0 + 8) * 72 + cl + 1] = v11;
            }
        }
    }
    __syncthreads();

    // softmax: 128 tokens, 2 threads/token; write g_w as half
    {
        int tok = tid >> 1, q2 = tid & 1;
        float* row = lgs + tok * 72 + q2 * 32;
        float m = -1e30f;
        #pragma unroll
        for (int s = 0; s < 32; s++) m = fmaxf(m, row[s]);
        m = fmaxf(m, __shfl_xor_sync(0xffffffffu, m, 1));
        float e[32];
        float sum = 0.f;
        #pragma unroll
        for (int s = 0; s < 32; s++) { e[s] = __expf(row[s] - m); sum += e[s]; }
        sum += __shfl_xor_sync(0xffffffffu, sum, 1);
        float inv = 1.f / sum;
        float v[32];
        #pragma unroll
        for (int s = 0; s < 32; s++) { v[s] = e[s] * inv; row[s] = tf32r(v[s]); }
        __half* gw = g_w + (size_t)(b * NN + n0 + tok) * INNERR + h * 64 + q2 * 32;
        uint4* gp = (uint4*)gw;
        gp[0] = make_uint4(ph2(v[0], v[1]), ph2(v[2], v[3]), ph2(v[4], v[5]), ph2(v[6], v[7]));
        gp[1] = make_uint4(ph2(v[8], v[9]), ph2(v[10], v[11]), ph2(v[12], v[13]), ph2(v[14], v[15]));
        gp[2] = make_uint4(ph2(v[16], v[17]), ph2(v[18], v[19]), ph2(v[20], v[21]), ph2(v[22], v[23]));
        gp[3] = make_uint4(ph2(v[24], v[25]), ph2(v[26], v[27]), ph2(v[28], v[29]), ph2(v[30], v[31]));
    }
    __syncthreads();

    // slice_norm
    if (tid < 64) {
        float ns = 0.f;
        #pragma unroll 8
        for (int t = 0; t < 128; t++) ns += lgs[t * 72 + tid];
        atomicAdd(&g_norm[((size_t)b * HH + h) * 64 + tid], ns);
    }

    // tok[s][d] += sum_t w[t][s] * fx[t][d]  (tf32 mma)
    {
        float a2[4][4];
        #pragma unroll
        for (int i = 0; i < 4; i++)
            #pragma unroll
            for (int j = 0; j < 4; j++) a2[i][j] = 0.f;
        const int m0 = (wid & 3) * 16;
        const int dh = (wid >> 2) * 32;
        #pragma unroll
        for (int ks = 0; ks < 16; ks++) {
            const int kb = ks * 8;
            uint32_t A0 = FB(lgs[(kb + k4) * 72 + m0 + g]);
            uint32_t A1 = FB(lgs[(kb + k4) * 72 + m0 + g + 8]);
            uint32_t A2 = FB(lgs[(kb + k4 + 4) * 72 + m0 + g]);
            uint32_t A3 = FB(lgs[(kb + k4 + 4) * 72 + m0 + g + 8]);
            #pragma unroll
            for (int ni = 0; ni < 4; ni++) {
                int c = dh + ni * 8 + g;
                uint32_t B0 = FB(fxs[(kb + k4) * 72 + c]);
                uint32_t B1 = FB(fxs[(kb + k4 + 4) * 72 + c]);
                mmat(a2[ni], A0, A1, A2, A3, B0, B1);
            }
        }
        float* gt = g_tok + (size_t)((b * HH + h) * 64) * 64;
        #pragma unroll
        for (int ni = 0; ni < 4; ni++) {
            int s0 = m0 + g, c0 = dh + ni * 8 + k4 * 2;
            atomicAdd(gt + s0 * 64 + c0,           a2[ni][0]);
            atomicAdd(gt + s0 * 64 + c0 + 1,       a2[ni][1]);
            atomicAdd(gt + (s0 + 8) * 64 + c0,     a2[ni][2]);
            atomicAdd(gt + (s0 + 8) * 64 + c0 + 1, a2[ni][3]);
        }
    }
}

// ---------------- k2: cross-slice attention + fused M precompute ----------------
__device__ __forceinline__ void gemm16(const float* __restrict__ A, int sa,
                                       const float* __restrict__ B /* stride 68 */,
                                       int tr, int tc, float o[4][4]) {
    #pragma unroll
    for (int i = 0; i < 4; i++)
        #pragma unroll
        for (int j = 0; j < 4; j++) o[i][j] = 0.f;
    #pragma unroll 4
    for (int e = 0; e < 64; e++) {
        float4 bv = *(const float4*)(B + e * 68 + tc * 4);
        #pragma unroll
        for (int i = 0; i < 4; i++) {
            float a = A[(tr * 4 + i) * sa + e];
            o[i][0] += a * bv.x; o[i][1] += a * bv.y;
            o[i][2] += a * bv.z; o[i][3] += a * bv.w;
        }
    }
}

// grid (H, B), block 256, dyn smem = 156160 B
__global__ void k2(const float* __restrict__ Wq, const float* __restrict__ Wk,
                   const float* __restrict__ Wv, const float* __restrict__ ascale_p,
                   const float* __restrict__ srs_p, const float* __restrict__ Wout) {
    extern __shared__ float sm[];
    float* rn   = sm;                    // [512]
    float* tokn = sm + 512;              // [64][65]
    float* kv   = sm + 4672;             // [64][65]
    float* wq   = sm + 8832;             // [64][68] transposed [e][d]
    float* wk   = sm + 13184;            // [64][68]
    float* wv   = sm + 17536;            // [64][68]
    float* qq   = sm + 21888;            // [64][65]
    float* kkt  = sm + 26048;            // [64][68]
    float* vv   = sm + 30400;            // [64][68]
    float* att  = sm + 34752;            // [64][65]
    float* nqi  = sm + 38912;            // [64]
    float* nki  = sm + 38976;            // [64]
    const int h = blockIdx.x, b = blockIdx.y;
    const int tid = threadIdx.x;
    const int tr = tid >> 4, tc = tid & 15;

    for (int i = tid; i < 512; i += 256) rn[i] = __frcp_rn(g_norm[b * 512 + i] + 1e-5f);
    for (int i = tid; i < 4096; i += 256) {
        int e = i & 63, d = i >> 6;
        wq[e * 68 + d] = Wq[d * 64 + e];
        wk[e * 68 + d] = Wk[d * 64 + e];
        wv[e * 68 + d] = Wv[d * 64 + e];
    }
    __syncthreads();

    for (int i = tid; i < 4096; i += 256) {
        int s = i >> 6, d = i & 63;
        float accv = 0.f;
        #pragma unroll
        for (int hh = 0; hh < 8; hh++)
            accv += g_tok[((b * 8 + hh) * 64 + s) * 64 + d] * rn[hh * 64 + s];
        kv[s * 65 + d] = accv * 0.125f;
        tokn[s * 65 + d] = g_tok[((b * 8 + h) * 64 + s) * 64 + d] * rn[h * 64 + s];
    }
    __syncthreads();

    // merged q/k/v GEMMs
    {
        float oq[4][4], ok[4][4], ov[4][4];
        #pragma unroll
        for (int i = 0; i < 4; i++)
            #pragma unroll
            for (int j = 0; j < 4; j++) { oq[i][j] = 0.f; ok[i][j] = 0.f; ov[i][j] = 0.f; }
        #pragma unroll 2
        for (int e = 0; e < 64; e++) {
            float4 bq = *(const float4*)(wq + e * 68 + tc * 4);
            float4 bk = *(const float4*)(wk + e * 68 + tc * 4);
            float4 bv = *(const float4*)(wv + e * 68 + tc * 4);
            #pragma unroll
            for (int i = 0; i < 4; i++) {
                float aq = tokn[(tr * 4 + i) * 65 + e];
                float ak = kv[(tr * 4 + i) * 65 + e];
                oq[i][0] += aq * bq.x; oq[i][1] += aq * bq.y; oq[i][2] += aq * bq.z; oq[i][3] += aq * bq.w;
                ok[i][0] += ak * bk.x; ok[i][1] += ak * bk.y; ok[i][2] += ak * bk.z; ok[i][3] += ak * bk.w;
                ov[i][0] += ak * bv.x; ov[i][1] += ak * bv.y; ov[i][2] += ak * bv.z; ov[i][3] += ak * bv.w;
            }
        }
        #pragma unroll
        for (int i = 0; i < 4; i++)
            #pragma unroll
            for (int j = 0; j < 4; j++) {
                qq[(tr * 4 + i) * 65 + tc * 4 + j]  = oq[i][j];
                kkt[(tc * 4 + j) * 68 + tr * 4 + i] = ok[i][j];
                vv[(tr * 4 + i) * 68 + tc * 4 + j]  = ov[i][j];
            }
    }
    __syncthreads();

    if (tid < 64) {
        float s2 = 0.f;
        #pragma unroll 8
        for (int d = 0; d < 64; d++) { float v = qq[tid * 65 + d]; s2 += v * v; }
        nqi[tid] = rsqrtf(fmaxf(s2, 1e-24f));
    } else if (tid < 128) {
        int s = tid - 64;
        float s2 = 0.f;
        #pragma unroll 8
        for (int d = 0; d < 64; d++) { float v = kkt[d * 68 + s]; s2 += v * v; }
        nki[s] = rsqrtf(fmaxf(s2, 1e-24f));
    }
    __syncthreads();

    float o[4][4];
    gemm16(qq, 65, kkt, tr, tc, o);
    {
        float asc = ascale_p[h];
        float rq[4], rk[4];
        #pragma unroll
        for (int i = 0; i < 4; i++) rq[i] = asc * nqi[tr * 4 + i];
        #pragma unroll
        for (int j = 0; j < 4; j++) rk[j] = nki[tc * 4 + j];
        #pragma unroll
        for (int i = 0; i < 4; i++)
            #pragma unroll
            for (int j = 0; j < 4; j++)
                att[(tr * 4 + i) * 65 + tc * 4 + j] = o[i][j] * rq[i] * rk[j];
    }
    __syncthreads();

    // softmax rows of att
    {
        int gg = tid >> 2, q4 = tid & 3;
        float* row = att + gg * 65;
        float m = -1e30f;
        #pragma unroll
        for (int s = 0; s < 16; s++) m = fmaxf(m, row[q4 * 16 + s]);
        m = fmaxf(m, __shfl_xor_sync(0xffffffffu, m, 1));
        m = fmaxf(m, __shfl_xor_sync(0xffffffffu, m, 2));
        float e[16];
        float sum = 0.f;
        #pragma unroll
        for (int s = 0; s < 16; s++) { e[s] = __expf(row[q4 * 16 + s] - m); sum += e[s]; }
        sum += __shfl_xor_sync(0xffffffffu, sum, 1);
        sum += __shfl_xor_sync(0xffffffffu, sum, 2);
        float inv = 1.f / sum;
        #pragma unroll
        for (int s = 0; s < 16; s++) row[q4 * 16 + s] = e[s] * inv;
    }
    __syncthreads();

    // out_tok = att @ v + sr * tokn -> transposed ots_t[d][s]
    gemm16(att, 65, vv, tr, tc, o);
    float* ots_t = qq;   // [64 d][68]
    {
        float sr = srs_p[0];
        #pragma unroll
        for (int i = 0; i < 4; i++)
            #pragma unroll
            for (int j = 0; j < 4; j++) {
                int gg = tr * 4 + i, d = tc * 4 + j;
                ots_t[d * 68 + gg] = o[i][j] + sr * tokn[gg * 65 + d];
            }
    }
    __syncthreads();

    // fused M precompute: M[b][o][h*64+s] = sum_d Wout[o][h*64+d] * out_tok[s][d]
    float* wos = sm;     // [256][68]
    for (int i = tid; i < 16384; i += 256) {
        int oo = i >> 6, d = i & 63;
        wos[oo * 68 + d] = Wout[(size_t)oo * INNERR + h * 64 + d];
    }
    __syncthreads();

    {
        const int tcs = tid & 3;
        const int tro = tid >> 2;
        float accm[4][16];
        #pragma unroll
        for (int i = 0; i < 4; i++)
            #pragma unroll
            for (int j = 0; j < 16; j++) accm[i][j] = 0.f;
        #pragma unroll 2
        for (int d = 0; d < 64; d++) {
            float4 s0 = *(const float4*)(ots_t + d * 68 + tcs * 16);
            float4 s1 = *(const float4*)(ots_t + d * 68 + tcs * 16 + 4);
            float4 s2 = *(const float4*)(ots_t + d * 68 + tcs * 16 + 8);
            float4 s3 = *(const float4*)(ots_t + d * 68 + tcs * 16 + 12);
            #pragma unroll
            for (int i = 0; i < 4; i++) {
                float a = wos[(tro * 4 + i) * 68 + d];
                accm[i][0]  += a * s0.x; accm[i][1]  += a * s0.y; accm[i][2]  += a * s0.z; accm[i][3]  += a * s0.w;
                accm[i][4]  += a * s1.x; accm[i][5]  += a * s1.y; accm[i][6]  += a * s1.z; accm[i][7]  += a * s1.w;
                accm[i][8]  += a * s2.x; accm[i][9]  += a * s2.y; accm[i][10] += a * s2.z; accm[i][11] += a * s2.w;
                accm[i][12] += a * s3.x; accm[i][13] += a * s3.y; accm[i][14] += a * s3.z; accm[i][15] += a * s3.w;
            }
        }
        #pragma unroll
        for (int i = 0; i < 4; i++) {
            int oo = tro * 4 + i;
            __half* mp = g_M + ((size_t)(b * DIMM + oo)) * INNERR + h * 64 + tcs * 16;
            uint4 p0, p1;
            p0.x = ph2(accm[i][0], accm[i][1]);   p0.y = ph2(accm[i][2], accm[i][3]);
            p0.z = ph2(accm[i][4], accm[i][5]);   p0.w = ph2(accm[i][6], accm[i][7]);
            p1.x = ph2(accm[i][8], accm[i][9]);   p1.y = ph2(accm[i][10], accm[i][11]);
            p1.z = ph2(accm[i][12], accm[i][13]); p1.w = ph2(accm[i][14], accm[i][15]);
            ((uint4*)mp)[0] = p0;
            ((uint4*)mp)[1] = p1;
        }
    }
}

// ---------------- pass 2: pipelined y = w @ M^T + bout via fp16 mma ----------------
// grid (2, N/128, B), block 256, dyn smem = 73728 B (2 stages)
__global__ __launch_bounds__(256, 2) void k3(const float* __restrict__ bout, float* __restrict__ out) {
    extern __shared__ float sm[];
    __half* base = (__half*)sm;
    const int cb = blockIdx.x, nt = blockIdx.y, b = blockIdx.z;
    const int tid = threadIdx.x;
    const int lane = tid & 31, wid = tid >> 5;
    const int wm = wid & 3, wn = wid >> 2;
    const int g = lane >> 2, k4 = lane & 3;
    const int n0 = nt * 128, col0 = cb * 128;
    const __half* wp = g_w + (size_t)(b * NN + n0) * INNERR;
    const __half* mp = g_M + (size_t)b * DIMM * INNERR + (size_t)col0 * INNERR;

    float acc[16][4];
    #pragma unroll
    for (int i = 0; i < 16; i++)
        #pragma unroll
        for (int j = 0; j < 4; j++) acc[i][j] = 0.f;

    auto issue = [&](int c) {
        __half* wt = base + (c & 1) * 18432;
        __half* ms = wt + 9216;
        int kc = c * 64;
        for (int i = tid; i < 1024; i += 256) {
            int t = i >> 3, v8 = i & 7;
            cpa16(wt + t * 72 + v8 * 8, wp + (size_t)t * INNERR + kc + v8 * 8);
            cpa16(ms + t * 72 + v8 * 8, mp + (size_t)t * INNERR + kc + v8 * 8);
        }
        CPA_COMMIT;
    };

    issue(0);
    for (int c = 0; c < 8; c++) {
        if (c + 1 < 8) { issue(c + 1); CPA_WAIT1; } else { CPA_WAIT0; }
        __syncthreads();
        __half* wt = base + (c & 1) * 18432;
        __half* ms = wt + 9216;
        #pragma unroll
        for (int ks = 0; ks < 4; ks++) {
            const int kb = ks * 16;
            uint32_t A[2][4];
            #pragma unroll
            for (int mi = 0; mi < 2; mi++) {
                int r = wm * 32 + mi * 16 + g;
                const __half* x0 = wt + r * 72 + kb;
                const __half* x1 = wt + (r + 8) * 72 + kb;
                A[mi][0] = *(const uint32_t*)(x0 + 2 * k4);
                A[mi][1] = *(const uint32_t*)(x1 + 2 * k4);
                A[mi][2] = *(const uint32_t*)(x0 + 2 * k4 + 8);
                A[mi][3] = *(const uint32_t*)(x1 + 2 * k4 + 8);
            }
            #pragma unroll
            for (int ni = 0; ni < 8; ni++) {
                int cc = wn * 64 + ni * 8 + g;
                const __half* bp = ms + cc * 72 + kb;
                uint32_t B0 = *(const uint32_t*)(bp + 2 * k4);
                uint32_t B1 = *(const uint32_t*)(bp + 2 * k4 + 8);
                mmah(acc[0 * 8 + ni], A[0][0], A[0][1], A[0][2], A[0][3], B0, B1);
                mmah(acc[1 * 8 + ni], A[1][0], A[1][1], A[1][2], A[1][3], B0, B1);
            }
        }
        __syncthreads();
    }

    #pragma unroll
    for (int mi = 0; mi < 2; mi++) {
        #pragma unroll
        for (int ni = 0; ni < 8; ni++) {
            int cl = wn * 64 + ni * 8 + k4 * 2;
            float b0 = bout[col0 + cl], b1 = bout[col0 + cl + 1];
            int r0 = wm * 32 + mi * 16 + g;
            float* o0 = out + (size_t)(b * NN + n0 + r0) * DIMM + col0 + cl;
            float* o1 = out + (size_t)(b * NN + n0 + r0 + 8) * DIMM + col0 + cl;
            *(float2*)o0 = make_float2(acc[mi * 8 + ni][0] + b0, acc[mi * 8 + ni][1] + b1);
            *(float2*)o1 = make_float2(acc[mi * 8 + ni][2] + b0, acc[mi * 8 + ni][3] + b1);
        }
    }
}

// ---------------- launch ----------------
extern "C" void kernel_launch(void* const* d_in, const int* in_sizes, int n_in,
                              void* d_out, int out_size) {
    const float* x           = (const float*)d_in[0];
    const float* Wx          = (const float*)d_in[1];
    const float* bx          = (const float*)d_in[2];
    const float* Wfx         = (const float*)d_in[3];
    const float* bfx         = (const float*)d_in[4];
    const float* Wslice      = (const float*)d_in[5];
    const float* bslice      = (const float*)d_in[6];
    const float* temperature = (const float*)d_in[7];
    const float* Wq          = (const float*)d_in[8];
    const float* Wk          = (const float*)d_in[9];
    const float* Wv          = (const float*)d_in[10];
    const float* attn_scale  = (const float*)d_in[11];
    const float* srs         = (const float*)d_in[12];
    const float* Wout        = (const float*)d_in[13];
    const float* bout        = (const float*)d_in[14];
    float* out = (float*)d_out;

    const int K1S = 2 * 128 * 72 * (int)sizeof(float);   // 73728
    const int K2S = 39040 * (int)sizeof(float);          // 156160
    const int K3S = 2 * 128 * 72 * (int)sizeof(float) / 2;  // 73728 bytes (2 half stages)
    cudaFuncSetAttribute(k1, cudaFuncAttributeMaxDynamicSharedMemorySize, K1S);
    cudaFuncSetAttribute(k2, cudaFuncAttributeMaxDynamicSharedMemorySize, K2S);
    cudaFuncSetAttribute(k3, cudaFuncAttributeMaxDynamicSharedMemorySize, 73728);

    k_conv<<<8192, 256>>>(x);
    k_prep<<<dim3(HH, DIMM), 128>>>(Wx, bx, Wfx, bfx, Wslice, bslice, temperature);
    k1<<<dim3(HH, NN / 128, BB), 256, K1S>>>();
    k2<<<dim3(HH, BB), 256, K2S>>>(Wq, Wk, Wv, attn_scale, srs, Wout);
    k3<<<dim3(2, NN / 128, BB), 256, 73728>>>(bout, out);
}